// round 2
// baseline (speedup 1.0000x reference)
#include <cuda_runtime.h>
#include <math.h>

#define TT 64
#define BB 2048
#define OBS 48
#define HH 256
#define G4 1024
#define M1 512
#define M2 256
#define AA 12
#define TB (TT*BB)

#define LOG2PI 1.8378770664093453f

// ---------------- scratch (device globals: allocation-free) ----------------
__device__ float g_xg[(size_t)TB * G4];   // 512 MB
__device__ float g_hs[(size_t)TB * HH];   // 128 MB
__device__ float g_c[(size_t)BB * HH];    // 2 MB
__device__ float g_ln[(size_t)TB * HH];   // 128 MB
__device__ float g_y1[(size_t)TB * M1];   // 256 MB
__device__ float g_y2[(size_t)TB * M2];   // 128 MB

// ---------------- xg = x @ W_ih^T + b_ih + b_hh ----------------
// M=TB, N=G4, K=OBS(48). BM=64, BN=64, one K pass.
__global__ __launch_bounds__(256) void xg_kernel(
    const float* __restrict__ x, const float* __restrict__ W_ih,
    const float* __restrict__ b_ih, const float* __restrict__ b_hh)
{
    __shared__ float xs[64][OBS + 1];
    __shared__ float ws[64][OBS + 1];
    int n0 = blockIdx.x * 64;
    int c0 = blockIdx.y * 64;
    int tid = threadIdx.x;
    for (int i = tid; i < 64 * OBS; i += 256) {
        int r = i / OBS, k = i % OBS;
        xs[r][k] = x[(size_t)(n0 + r) * OBS + k];
    }
    for (int i = tid; i < 64 * OBS; i += 256) {
        int r = i / OBS, k = i % OBS;
        ws[r][k] = W_ih[(size_t)(c0 + r) * OBS + k];
    }
    __syncthreads();
    int tx = tid & 15, ty = tid >> 4;
    float acc[4][4] = {};
    for (int k = 0; k < OBS; k++) {
        float a[4], b[4];
#pragma unroll
        for (int r = 0; r < 4; r++) a[r] = xs[ty * 4 + r][k];
#pragma unroll
        for (int c = 0; c < 4; c++) b[c] = ws[tx * 4 + c][k];
#pragma unroll
        for (int r = 0; r < 4; r++)
#pragma unroll
            for (int c = 0; c < 4; c++) acc[r][c] += a[r] * b[c];
    }
#pragma unroll
    for (int c = 0; c < 4; c++) {
        int cc = c0 + tx * 4 + c;
        float bias = b_ih[cc] + b_hh[cc];
#pragma unroll
        for (int r = 0; r < 4; r++)
            g_xg[(size_t)(n0 + ty * 4 + r) * G4 + cc] = acc[r][c] + bias;
    }
}

// ---------------- one LSTM step ----------------
// g = xg[t] + (h*keep) @ W_hh^T ; gates ; c,h update. BM=32 (batch), BN=32 (j),
// each thread: 4 batch rows x 4 gates for one j.
__global__ __launch_bounds__(256) void lstm_step(
    const float* __restrict__ h0, const float* __restrict__ c0,
    const int* __restrict__ done, const float* __restrict__ W_hh, int t)
{
    __shared__ float hs_s[32][HH];       // 32 KB
    __shared__ float ws[4][32][17];      // 8.5 KB (K tile = 16)
    __shared__ float keep[32];

    const float* hprev = (t == 0) ? h0 : (g_hs + (size_t)(t - 1) * BB * HH);
    const float* cprev = (t == 0) ? c0 : g_c;
    float* hout = g_hs + (size_t)t * BB * HH;
    const float* xg_t = g_xg + (size_t)t * BB * G4;
    const int* done_t = done + (size_t)t * BB;

    int b0 = blockIdx.x * 32;
    int j0 = blockIdx.y * 32;
    int tid = threadIdx.x;
    if (tid < 32) keep[tid] = 1.0f - (float)done_t[b0 + tid];
    __syncthreads();

    // load masked h rows (full K), vectorized
    for (int i = tid; i < 32 * (HH / 4); i += 256) {
        int r = i / (HH / 4);
        int k4 = i % (HH / 4);
        float4 v = ((const float4*)hprev)[(size_t)(b0 + r) * (HH / 4) + k4];
        float m = keep[r];
        v.x *= m; v.y *= m; v.z *= m; v.w *= m;
        ((float4*)&hs_s[r][0])[k4] = v;
    }

    int tx = tid & 31, ty = tid >> 5; // tx = j in tile, ty = 0..7
    float acc[4][4] = {};
    for (int kt = 0; kt < HH; kt += 16) {
        __syncthreads();
        for (int i = tid; i < 4 * 32 * 16; i += 256) {
            int gt = i >> 9;
            int j = (i >> 4) & 31;
            int k = i & 15;
            ws[gt][j][k] = W_hh[(size_t)(gt * HH + j0 + j) * HH + kt + k];
        }
        __syncthreads();
#pragma unroll
        for (int k = 0; k < 16; k++) {
            float wv[4], hv[4];
#pragma unroll
            for (int gt = 0; gt < 4; gt++) wv[gt] = ws[gt][tx][k];
#pragma unroll
            for (int r = 0; r < 4; r++) hv[r] = hs_s[ty + 8 * r][kt + k];
#pragma unroll
            for (int r = 0; r < 4; r++)
#pragma unroll
                for (int gt = 0; gt < 4; gt++) acc[r][gt] += hv[r] * wv[gt];
        }
    }

    int j = j0 + tx;
#pragma unroll
    for (int r = 0; r < 4; r++) {
        int b = b0 + ty + 8 * r;
        size_t base = (size_t)b * G4;
        float gi = acc[r][0] + xg_t[base + j];
        float gf = acc[r][1] + xg_t[base + HH + j];
        float gg = acc[r][2] + xg_t[base + 2 * HH + j];
        float go = acc[r][3] + xg_t[base + 3 * HH + j];
        float si = 1.0f / (1.0f + expf(-gi));
        float sf = 1.0f / (1.0f + expf(-gf));
        float tg = tanhf(gg);
        float so = 1.0f / (1.0f + expf(-go));
        float cold = cprev[(size_t)b * HH + j] * keep[ty + 8 * r];
        float cn = sf * cold + si * tg;
        float hn = so * tanhf(cn);
        g_c[(size_t)b * HH + j] = cn;
        hout[(size_t)b * HH + j] = hn;
    }
}

// ---------------- LayerNorm: warp per row ----------------
__global__ __launch_bounds__(256) void ln_kernel(
    const float* __restrict__ gamma, const float* __restrict__ beta)
{
    int row = blockIdx.x * 8 + (threadIdx.x >> 5);
    int lane = threadIdx.x & 31;
    const float* hr = g_hs + (size_t)row * HH;
    float v[8];
    float s = 0.0f;
#pragma unroll
    for (int i = 0; i < 8; i++) { v[i] = hr[lane + 32 * i]; s += v[i]; }
#pragma unroll
    for (int o = 16; o; o >>= 1) s += __shfl_xor_sync(0xffffffffu, s, o);
    float mu = s * (1.0f / HH);
    float var = 0.0f;
#pragma unroll
    for (int i = 0; i < 8; i++) { float d = v[i] - mu; var += d * d; }
#pragma unroll
    for (int o = 16; o; o >>= 1) var += __shfl_xor_sync(0xffffffffu, var, o);
    var *= (1.0f / HH);
    float inv = rsqrtf(var + 1e-5f);
    float* yr = g_ln + (size_t)row * HH;
#pragma unroll
    for (int i = 0; i < 8; i++) {
        int c = lane + 32 * i;
        yr[c] = (v[i] - mu) * inv * gamma[c] + beta[c];
    }
}

// ---------------- tiled GEMM + bias + ELU ----------------
// out[M,N] = ELU(Ain[M,K] @ W[K,N] + bias). BM=64, BN=64, BK=32.
template <int N, int K>
__global__ __launch_bounds__(256) void mlp_gemm(
    const float* __restrict__ Ain, const float* __restrict__ W,
    const float* __restrict__ bias, float* __restrict__ Out)
{
    __shared__ float a_s[64][33];
    __shared__ float b_s[32][64];
    int n0 = blockIdx.x * 64;
    int c0 = blockIdx.y * 64;
    int tid = threadIdx.x;
    int tx = tid & 15, ty = tid >> 4;
    float acc[4][4] = {};
    for (int kt = 0; kt < K; kt += 32) {
        __syncthreads();
        for (int i = tid; i < 64 * 32; i += 256) {
            int r = i >> 5, k = i & 31;
            a_s[r][k] = Ain[(size_t)(n0 + r) * K + kt + k];
        }
        for (int i = tid; i < 32 * 64; i += 256) {
            int k = i >> 6, c = i & 63;
            b_s[k][c] = W[(size_t)(kt + k) * N + c0 + c];
        }
        __syncthreads();
#pragma unroll
        for (int k = 0; k < 32; k++) {
            float4 bv = *reinterpret_cast<const float4*>(&b_s[k][tx * 4]);
            float bb[4] = {bv.x, bv.y, bv.z, bv.w};
#pragma unroll
            for (int r = 0; r < 4; r++) {
                float av = a_s[ty * 4 + r][k];
#pragma unroll
                for (int c = 0; c < 4; c++) acc[r][c] += av * bb[c];
            }
        }
    }
#pragma unroll
    for (int c = 0; c < 4; c++) {
        float bs_ = bias[c0 + tx * 4 + c];
#pragma unroll
        for (int r = 0; r < 4; r++) {
            float v = acc[r][c] + bs_;
            v = (v > 0.0f) ? v : expm1f(v);
            Out[(size_t)(n0 + ty * 4 + r) * N + c0 + tx * 4 + c] = v;
        }
    }
}

// ---------------- heads: mean, logp, entropy ----------------
// 16 rows per block, 24 dot products per row (12 mean + 12 logstd).
__global__ __launch_bounds__(384) void heads_kernel(
    const float* __restrict__ Wm, const float* __restrict__ bm,
    const float* __restrict__ Ws, const float* __restrict__ bs,
    float* __restrict__ out)
{
    __shared__ float wc[M2][24];       // 24 KB
    __shared__ float ys[16][M2 + 1];   // 16.1 KB
    __shared__ float ls[16][12];
    int tid = threadIdx.x;
    for (int i = tid; i < M2 * 12; i += 384) {
        int k = i / 12, o = i % 12;
        wc[k][o] = Wm[k * 12 + o];
        wc[k][o + 12] = Ws[k * 12 + o];
    }
    int n0 = blockIdx.x * 16;
    for (int i = tid; i < 16 * M2; i += 384) {
        int r = i >> 8, k = i & 255;
        ys[r][k] = g_y2[(size_t)(n0 + r) * M2 + k];
    }
    __syncthreads();
    int r = tid / 24, o = tid % 24;
    float acc = 0.0f;
#pragma unroll 8
    for (int k = 0; k < M2; k++) acc += ys[r][k] * wc[k][o];
    if (o < 12) {
        out[(size_t)(n0 + r) * 14 + o] = acc + bm[o];
    } else {
        float l = acc + bs[o - 12];
        l = fminf(fmaxf(l, -5.0f), 2.0f);
        ls[r][o - 12] = l;
    }
    __syncthreads();
    if (o == 0) {
        float S = 0.0f;
#pragma unroll
        for (int i = 0; i < 12; i++) S += ls[r][i];
        out[(size_t)(n0 + r) * 14 + 12] = -S - 6.0f * LOG2PI;
        out[(size_t)(n0 + r) * 14 + 13] = S + 6.0f + 6.0f * LOG2PI;
    }
}

// ---------------- launch ----------------
extern "C" void kernel_launch(void* const* d_in, const int* in_sizes, int n_in,
                              void* d_out, int out_size)
{
    const float *x, *h0, *c0, *W_ih, *W_hh, *b_ih, *b_hh, *ln_g, *ln_b;
    const float *W1, *b1, *W2, *b2, *Wm, *bm, *Ws, *bs;
    const int* done;

    if (in_sizes[1] == TT * BB) {
        // setup_inputs dict order: x, done, h0, c0, W_ih, W_hh, b_ih, b_hh,
        // ln_g, ln_b, W1, b1, W2, b2, Wm, bm, Ws, bs
        x = (const float*)d_in[0];  done = (const int*)d_in[1];
        h0 = (const float*)d_in[2]; c0 = (const float*)d_in[3];
        W_ih = (const float*)d_in[4]; W_hh = (const float*)d_in[5];
        b_ih = (const float*)d_in[6]; b_hh = (const float*)d_in[7];
        ln_g = (const float*)d_in[8]; ln_b = (const float*)d_in[9];
        W1 = (const float*)d_in[10]; b1 = (const float*)d_in[11];
        W2 = (const float*)d_in[12]; b2 = (const float*)d_in[13];
        Wm = (const float*)d_in[14]; bm = (const float*)d_in[15];
        Ws = (const float*)d_in[16]; bs = (const float*)d_in[17];
    } else {
        // reference() signature order: x, h0, c0, W_ih, W_hh, b_ih, b_hh,
        // ln_g, ln_b, W1, b1, W2, b2, Wm, bm, Ws, bs, done
        x = (const float*)d_in[0];
        h0 = (const float*)d_in[1]; c0 = (const float*)d_in[2];
        W_ih = (const float*)d_in[3]; W_hh = (const float*)d_in[4];
        b_ih = (const float*)d_in[5]; b_hh = (const float*)d_in[6];
        ln_g = (const float*)d_in[7]; ln_b = (const float*)d_in[8];
        W1 = (const float*)d_in[9];  b1 = (const float*)d_in[10];
        W2 = (const float*)d_in[11]; b2 = (const float*)d_in[12];
        Wm = (const float*)d_in[13]; bm = (const float*)d_in[14];
        Ws = (const float*)d_in[15]; bs = (const float*)d_in[16];
        done = (const int*)d_in[17];
    }

    float* out = (float*)d_out;

    float *p_ln, *p_y1, *p_y2;
    cudaGetSymbolAddress((void**)&p_ln, g_ln);
    cudaGetSymbolAddress((void**)&p_y1, g_y1);
    cudaGetSymbolAddress((void**)&p_y2, g_y2);

    // 1. input-side gate projections for all timesteps
    xg_kernel<<<dim3(TB / 64, G4 / 64), 256>>>(x, W_ih, b_ih, b_hh);

    // 2. sequential LSTM
    for (int t = 0; t < TT; t++)
        lstm_step<<<dim3(BB / 32, HH / 32), 256>>>(h0, c0, done, W_hh, t);

    // 3. LayerNorm
    ln_kernel<<<TB / 8, 256>>>(ln_g, ln_b);

    // 4. MLP
    mlp_gemm<M1, HH><<<dim3(TB / 64, M1 / 64), 256>>>(p_ln, W1, b1, p_y1);
    mlp_gemm<M2, M1><<<dim3(TB / 64, M2 / 64), 256>>>(p_y1, W2, b2, p_y2);

    // 5. heads
    heads_kernel<<<TB / 16, 384>>>(Wm, bm, Ws, bs, out);
}

// round 3
// speedup vs baseline: 3.4099x; 3.4099x over previous
#include <cuda_runtime.h>
#include <cuda_bf16.h>
#include <math.h>
#include <stdint.h>

#define TT 64
#define BB 2048
#define OBS 48
#define HH 256
#define G4 1024
#define KC 304            // combined K = HH + OBS
#define M1 512
#define M2 256
#define TB (TT*BB)
#define LOG2PI 1.8378770664093453f

typedef __nv_bfloat16 bf16;

// ---------------- scratch (device globals: allocation-free) ----------------
__device__ __align__(16) bf16 g_Wc[G4 * KC];          // combined [Whh|Wih], [n=j*4+g][k]
__device__ float            g_bias[G4];               // b_ih + b_hh, gate-interleaved
__device__ __align__(16) bf16 g_W1b[M1 * HH];         // [n][k]
__device__ __align__(16) bf16 g_W2b[M2 * M1];         // [n][k]
__device__ __align__(16) bf16 g_xb[(size_t)TB * OBS];
__device__ __align__(16) bf16 g_h0b[BB * HH];
__device__ __align__(16) bf16 g_hb[(size_t)TB * HH];  // all h outputs, bf16
__device__ float            g_c[BB * HH];
__device__ float            g_mu[TB];
__device__ float            g_rs[TB];
__device__ __align__(16) bf16 g_y1[(size_t)TB * M1];
__device__ __align__(16) bf16 g_y2[(size_t)TB * M2];

// ---------------- mma helper ----------------
__device__ __forceinline__ void mma16816(float c[4],
    uint32_t a0, uint32_t a1, uint32_t a2, uint32_t a3,
    uint32_t b0, uint32_t b1)
{
    asm volatile(
        "mma.sync.aligned.m16n8k16.row.col.f32.bf16.bf16.f32 "
        "{%0,%1,%2,%3}, {%4,%5,%6,%7}, {%8,%9}, {%0,%1,%2,%3};"
        : "+f"(c[0]), "+f"(c[1]), "+f"(c[2]), "+f"(c[3])
        : "r"(a0), "r"(a1), "r"(a2), "r"(a3), "r"(b0), "r"(b1));
}

__device__ __forceinline__ float sigmoidf_(float x) {
    return 1.0f / (1.0f + __expf(-x));
}

#define AS_STRIDE 24
#define BS_STRIDE 24
#define CS_STRIDE 132

// ---------------- prep kernels ----------------
__global__ void prep_wc(const float* __restrict__ W_hh, const float* __restrict__ W_ih,
                        const float* __restrict__ b_ih, const float* __restrict__ b_hh)
{
    int idx = blockIdx.x * blockDim.x + threadIdx.x;
    if (idx >= G4 * KC) return;
    int n = idx / KC, k = idx % KC;
    int g = n & 3, j = n >> 2;
    float v = (k < HH) ? W_hh[(size_t)(g * HH + j) * HH + k]
                       : W_ih[(size_t)(g * HH + j) * OBS + (k - HH)];
    g_Wc[idx] = __float2bfloat16(v);
    if (k == 0) g_bias[n] = b_ih[g * HH + j] + b_hh[g * HH + j];
}

__global__ void prep_w12(const float* __restrict__ W1, const float* __restrict__ W2)
{
    int idx = blockIdx.x * blockDim.x + threadIdx.x;
    if (idx >= M1 * HH + M2 * M1) return;
    if (idx < M1 * HH) {
        int n = idx / HH, k = idx % HH;     // W1: [HH][M1] -> [n][k]
        g_W1b[idx] = __float2bfloat16(W1[(size_t)k * M1 + n]);
    } else {
        int i = idx - M1 * HH;
        int n = i / M1, k = i % M1;         // W2: [M1][M2] -> [n][k]
        g_W2b[i] = __float2bfloat16(W2[(size_t)k * M2 + n]);
    }
}

__global__ void prep_xh(const float* __restrict__ x, const float* __restrict__ h0)
{
    size_t idx = (size_t)blockIdx.x * blockDim.x + threadIdx.x;
    size_t nx = (size_t)TB * OBS;
    if (idx < nx) g_xb[idx] = __float2bfloat16(x[idx]);
    else if (idx < nx + (size_t)BB * HH) {
        size_t i = idx - nx;
        g_h0b[i] = __float2bfloat16(h0[i]);
    }
}

// ---------------- LSTM step (bf16 mma) ----------------
// C[64 x 128] tile of gates = A[64 x 304] x B[304 x 128]
// A = [h*keep | x_t] bf16, B = gate-interleaved combined weights.
__global__ __launch_bounds__(256) void lstm_step_mma(
    const bf16* __restrict__ hprev, const float* __restrict__ cprev,
    const int* __restrict__ done_t, int t)
{
    __shared__ bf16  as[64 * AS_STRIDE];
    __shared__ bf16  bs[128 * BS_STRIDE];
    __shared__ float csm[64 * CS_STRIDE];
    __shared__ float bias_s[128];

    const int tid = threadIdx.x;
    const int b0 = blockIdx.x * 64;
    const int n0 = blockIdx.y * 128;
    const bf16* xb_t = g_xb + (size_t)t * BB * OBS;

    if (tid < 128) bias_s[tid] = g_bias[n0 + tid];

    // A loader: each thread fills 4 bf16 of one row per chunk
    const int arow = tid >> 2;
    const int aseg = tid & 3;
    const int keepA = 1 - done_t[b0 + arow];
    const bf16* hrow = hprev + (size_t)(b0 + arow) * HH + aseg * 4;
    const bf16* xrow = xb_t + (size_t)(b0 + arow) * OBS + aseg * 4;
    // B loader: each thread fills 8 bf16 of one n-row per chunk
    const int bn = tid >> 1;
    const int bh = tid & 1;
    const bf16* wrow = g_Wc + (size_t)(n0 + bn) * KC + bh * 8;

    const int lane = tid & 31;
    const int warp = tid >> 5;
    const int wm = warp & 1, wn = warp >> 1;    // 2 x 4 warp grid
    const int g8 = lane >> 2, t4 = lane & 3;

    float acc[2][4][4];
#pragma unroll
    for (int i = 0; i < 2; i++)
#pragma unroll
        for (int j = 0; j < 4; j++)
#pragma unroll
            for (int k = 0; k < 4; k++) acc[i][j][k] = 0.0f;

    // prefetch chunk 0
    uint2 aReg;
    uint4 bReg;
    {
        aReg = *(const uint2*)hrow;           // kt = 0 (< HH)
        if (!keepA) { aReg.x = 0u; aReg.y = 0u; }
        bReg = *(const uint4*)wrow;
    }

#pragma unroll 1
    for (int ch = 0; ch < KC / 16; ch++) {
        __syncthreads();
        *(uint2*)&as[arow * AS_STRIDE + aseg * 4] = aReg;
        *(uint4*)&bs[bn * BS_STRIDE + bh * 8]    = bReg;
        __syncthreads();

        if (ch < KC / 16 - 1) {
            int kt = (ch + 1) * 16;
            if (kt < HH) {
                aReg = *(const uint2*)(hrow + kt);
                if (!keepA) { aReg.x = 0u; aReg.y = 0u; }
            } else {
                aReg = *(const uint2*)(xrow + (kt - HH));
            }
            bReg = *(const uint4*)(wrow + kt);
        }

        uint32_t af[2][4];
#pragma unroll
        for (int am = 0; am < 2; am++) {
            const bf16* ap = &as[(wm * 32 + am * 16 + g8) * AS_STRIDE + t4 * 2];
            af[am][0] = *(const uint32_t*)ap;
            af[am][1] = *(const uint32_t*)(ap + 8 * AS_STRIDE);
            af[am][2] = *(const uint32_t*)(ap + 8);
            af[am][3] = *(const uint32_t*)(ap + 8 * AS_STRIDE + 8);
        }
#pragma unroll
        for (int an = 0; an < 4; an++) {
            const bf16* bp = &bs[(wn * 32 + an * 8 + g8) * BS_STRIDE + t4 * 2];
            uint32_t b0v = *(const uint32_t*)bp;
            uint32_t b1v = *(const uint32_t*)(bp + 8);
#pragma unroll
            for (int am = 0; am < 2; am++)
                mma16816(acc[am][an], af[am][0], af[am][1], af[am][2], af[am][3], b0v, b1v);
        }
    }

    // C -> smem
#pragma unroll
    for (int am = 0; am < 2; am++)
#pragma unroll
        for (int an = 0; an < 4; an++) {
            int r = wm * 32 + am * 16 + g8;
            int c = wn * 32 + an * 8 + t4 * 2;
            *(float2*)&csm[r * CS_STRIDE + c]       = make_float2(acc[am][an][0], acc[am][an][1]);
            *(float2*)&csm[(r + 8) * CS_STRIDE + c] = make_float2(acc[am][an][2], acc[am][an][3]);
        }
    __syncthreads();

    // gate fusion epilogue: 64 rows x 32 j per block
    bf16* hout = g_hb + (size_t)t * BB * HH;
    const int j0 = n0 >> 2;
#pragma unroll
    for (int i = 0; i < 8; i++) {
        int p = i * 256 + tid;
        int bl = p >> 5, jl = p & 31;
        float4 gq = *(const float4*)&csm[bl * CS_STRIDE + jl * 4];
        float gi = gq.x + bias_s[jl * 4 + 0];
        float gf = gq.y + bias_s[jl * 4 + 1];
        float gg = gq.z + bias_s[jl * 4 + 2];
        float go = gq.w + bias_s[jl * 4 + 3];
        int b = b0 + bl;
        int j = j0 + jl;
        float kb = 1.0f - (float)done_t[b];
        float cold = cprev[b * HH + j] * kb;
        float cn = sigmoidf_(gf) * cold + sigmoidf_(gi) * tanhf(gg);
        float hn = sigmoidf_(go) * tanhf(cn);
        g_c[b * HH + j] = cn;
        hout[(size_t)b * HH + j] = __float2bfloat16(hn);
    }
}

// ---------------- LayerNorm stats (per row of g_hb) ----------------
__global__ __launch_bounds__(256) void ln_stats()
{
    int row = blockIdx.x * 8 + (threadIdx.x >> 5);
    int lane = threadIdx.x & 31;
    uint4 u = *(const uint4*)(g_hb + (size_t)row * HH + lane * 8);
    const __nv_bfloat162* p = (const __nv_bfloat162*)&u;
    float s = 0.0f, s2 = 0.0f;
#pragma unroll
    for (int i = 0; i < 4; i++) {
        float2 f = __bfloat1622float2(p[i]);
        s += f.x + f.y;
        s2 += f.x * f.x + f.y * f.y;
    }
#pragma unroll
    for (int o = 16; o; o >>= 1) {
        s  += __shfl_xor_sync(0xffffffffu, s, o);
        s2 += __shfl_xor_sync(0xffffffffu, s2, o);
    }
    if (lane == 0) {
        float mu = s * (1.0f / HH);
        float var = s2 * (1.0f / HH) - mu * mu;
        g_mu[row] = mu;
        g_rs[row] = rsqrtf(var + 1e-5f);
    }
}

// ---------------- MLP GEMM (bf16 mma): Out = ELU(A @ B^T + bias) ----------------
// A rows optionally LayerNorm-transformed on load. B stored [n][k].
template <int KD, int ND, bool LNA>
__global__ __launch_bounds__(256) void mlp_mma(
    const bf16* __restrict__ A, const bf16* __restrict__ Bw,
    const float* __restrict__ bias, bf16* __restrict__ Out,
    const float* __restrict__ gamma, const float* __restrict__ beta)
{
    __shared__ bf16 as[64 * AS_STRIDE];
    __shared__ bf16 bs[128 * BS_STRIDE];

    const int tid = threadIdx.x;
    const size_t m0 = (size_t)blockIdx.x * 64;
    const int n0 = blockIdx.y * 128;

    const int arow = tid >> 2;
    const int aseg = tid & 3;
    const bf16* arp = A + (m0 + arow) * KD + aseg * 4;
    float mur = 0.0f, rsr = 0.0f;
    if (LNA) { mur = g_mu[m0 + arow]; rsr = g_rs[m0 + arow]; }

    const int bn = tid >> 1;
    const int bh = tid & 1;
    const bf16* wrow = Bw + (size_t)(n0 + bn) * KD + bh * 8;

    const int lane = tid & 31;
    const int warp = tid >> 5;
    const int wm = warp & 1, wn = warp >> 1;
    const int g8 = lane >> 2, t4 = lane & 3;

    float acc[2][4][4];
#pragma unroll
    for (int i = 0; i < 2; i++)
#pragma unroll
        for (int j = 0; j < 4; j++)
#pragma unroll
            for (int k = 0; k < 4; k++) acc[i][j][k] = 0.0f;

    uint2 aReg;
    uint4 bReg;

    auto loadA = [&](int kt) {
        uint2 v = *(const uint2*)(arp + kt);
        if (LNA) {
            __nv_bfloat162* vp = (__nv_bfloat162*)&v;
            int kb = kt + aseg * 4;
            float2 f0 = __bfloat1622float2(vp[0]);
            float2 f1 = __bfloat1622float2(vp[1]);
            f0.x = (f0.x - mur) * rsr * __ldg(&gamma[kb + 0]) + __ldg(&beta[kb + 0]);
            f0.y = (f0.y - mur) * rsr * __ldg(&gamma[kb + 1]) + __ldg(&beta[kb + 1]);
            f1.x = (f1.x - mur) * rsr * __ldg(&gamma[kb + 2]) + __ldg(&beta[kb + 2]);
            f1.y = (f1.y - mur) * rsr * __ldg(&gamma[kb + 3]) + __ldg(&beta[kb + 3]);
            vp[0] = __floats2bfloat162_rn(f0.x, f0.y);
            vp[1] = __floats2bfloat162_rn(f1.x, f1.y);
        }
        aReg = v;
    };

    loadA(0);
    bReg = *(const uint4*)wrow;

#pragma unroll 1
    for (int ch = 0; ch < KD / 16; ch++) {
        __syncthreads();
        *(uint2*)&as[arow * AS_STRIDE + aseg * 4] = aReg;
        *(uint4*)&bs[bn * BS_STRIDE + bh * 8]    = bReg;
        __syncthreads();

        if (ch < KD / 16 - 1) {
            loadA((ch + 1) * 16);
            bReg = *(const uint4*)(wrow + (ch + 1) * 16);
        }

        uint32_t af[2][4];
#pragma unroll
        for (int am = 0; am < 2; am++) {
            const bf16* ap = &as[(wm * 32 + am * 16 + g8) * AS_STRIDE + t4 * 2];
            af[am][0] = *(const uint32_t*)ap;
            af[am][1] = *(const uint32_t*)(ap + 8 * AS_STRIDE);
            af[am][2] = *(const uint32_t*)(ap + 8);
            af[am][3] = *(const uint32_t*)(ap + 8 * AS_STRIDE + 8);
        }
#pragma unroll
        for (int an = 0; an < 4; an++) {
            const bf16* bp = &bs[(wn * 32 + an * 8 + g8) * BS_STRIDE + t4 * 2];
            uint32_t b0v = *(const uint32_t*)bp;
            uint32_t b1v = *(const uint32_t*)(bp + 8);
#pragma unroll
            for (int am = 0; am < 2; am++)
                mma16816(acc[am][an], af[am][0], af[am][1], af[am][2], af[am][3], b0v, b1v);
        }
    }

    // epilogue: bias + ELU + pack bf16, direct to global
#pragma unroll
    for (int am = 0; am < 2; am++)
#pragma unroll
        for (int an = 0; an < 4; an++) {
            size_t r = m0 + wm * 32 + am * 16 + g8;
            int c = n0 + wn * 32 + an * 8 + t4 * 2;
            float bc0 = __ldg(&bias[c]), bc1 = __ldg(&bias[c + 1]);
            float v0 = acc[am][an][0] + bc0;
            float v1 = acc[am][an][1] + bc1;
            v0 = (v0 > 0.0f) ? v0 : expm1f(v0);
            v1 = (v1 > 0.0f) ? v1 : expm1f(v1);
            *(__nv_bfloat162*)(Out + r * ND + c) = __floats2bfloat162_rn(v0, v1);
            float v2 = acc[am][an][2] + bc0;
            float v3 = acc[am][an][3] + bc1;
            v2 = (v2 > 0.0f) ? v2 : expm1f(v2);
            v3 = (v3 > 0.0f) ? v3 : expm1f(v3);
            *(__nv_bfloat162*)(Out + (r + 8) * ND + c) = __floats2bfloat162_rn(v2, v3);
        }
}

// ---------------- heads: mean, logp, entropy ----------------
__global__ __launch_bounds__(384) void heads_kernel(
    const float* __restrict__ Wm, const float* __restrict__ bm,
    const float* __restrict__ Ws, const float* __restrict__ bs,
    float* __restrict__ out)
{
    __shared__ float wc[M2][24];
    __shared__ float ys[16][M2 + 1];
    __shared__ float ls[16][12];
    int tid = threadIdx.x;
    for (int i = tid; i < M2 * 12; i += 384) {
        int k = i / 12, o = i % 12;
        wc[k][o] = Wm[i];
        wc[k][o + 12] = Ws[i];
    }
    int n0 = blockIdx.x * 16;
    for (int i = tid; i < 16 * 32; i += 384) {
        int r = i >> 5, seg = i & 31;
        uint4 u = *(const uint4*)(g_y2 + (size_t)(n0 + r) * M2 + seg * 8);
        const __nv_bfloat162* p = (const __nv_bfloat162*)&u;
#pragma unroll
        for (int q = 0; q < 4; q++) {
            float2 f = __bfloat1622float2(p[q]);
            ys[r][seg * 8 + 2 * q]     = f.x;
            ys[r][seg * 8 + 2 * q + 1] = f.y;
        }
    }
    __syncthreads();
    int r = tid / 24, o = tid % 24;
    float acc = 0.0f;
#pragma unroll 8
    for (int k = 0; k < M2; k++) acc += ys[r][k] * wc[k][o];
    if (o < 12) {
        out[(size_t)(n0 + r) * 14 + o] = acc + bm[o];
    } else {
        float l = acc + bs[o - 12];
        l = fminf(fmaxf(l, -5.0f), 2.0f);
        ls[r][o - 12] = l;
    }
    __syncthreads();
    if (o == 0) {
        float S = 0.0f;
#pragma unroll
        for (int i = 0; i < 12; i++) S += ls[r][i];
        out[(size_t)(n0 + r) * 14 + 12] = -S - 6.0f * LOG2PI;
        out[(size_t)(n0 + r) * 14 + 13] = S + 6.0f + 6.0f * LOG2PI;
    }
}

// ---------------- launch ----------------
extern "C" void kernel_launch(void* const* d_in, const int* in_sizes, int n_in,
                              void* d_out, int out_size)
{
    const float *x, *h0, *c0, *W_ih, *W_hh, *b_ih, *b_hh, *ln_g, *ln_b;
    const float *W1, *b1, *W2, *b2, *Wm, *bm, *Ws, *bs;
    const int* done;

    if (in_sizes[1] == TT * BB) {
        // setup_inputs dict order
        x = (const float*)d_in[0];  done = (const int*)d_in[1];
        h0 = (const float*)d_in[2]; c0 = (const float*)d_in[3];
        W_ih = (const float*)d_in[4]; W_hh = (const float*)d_in[5];
        b_ih = (const float*)d_in[6]; b_hh = (const float*)d_in[7];
        ln_g = (const float*)d_in[8]; ln_b = (const float*)d_in[9];
        W1 = (const float*)d_in[10]; b1 = (const float*)d_in[11];
        W2 = (const float*)d_in[12]; b2 = (const float*)d_in[13];
        Wm = (const float*)d_in[14]; bm = (const float*)d_in[15];
        Ws = (const float*)d_in[16]; bs = (const float*)d_in[17];
    } else {
        // reference() signature order
        x = (const float*)d_in[0];
        h0 = (const float*)d_in[1]; c0 = (const float*)d_in[2];
        W_ih = (const float*)d_in[3]; W_hh = (const float*)d_in[4];
        b_ih = (const float*)d_in[5]; b_hh = (const float*)d_in[6];
        ln_g = (const float*)d_in[7]; ln_b = (const float*)d_in[8];
        W1 = (const float*)d_in[9];  b1 = (const float*)d_in[10];
        W2 = (const float*)d_in[11]; b2 = (const float*)d_in[12];
        Wm = (const float*)d_in[13]; bm = (const float*)d_in[14];
        Ws = (const float*)d_in[15]; bs = (const float*)d_in[16];
        done = (const int*)d_in[17];
    }

    float* out = (float*)d_out;

    bf16 *p_hb, *p_h0b, *p_W1b, *p_W2b, *p_y1, *p_y2;
    float* p_c;
    cudaGetSymbolAddress((void**)&p_hb, g_hb);
    cudaGetSymbolAddress((void**)&p_h0b, g_h0b);
    cudaGetSymbolAddress((void**)&p_W1b, g_W1b);
    cudaGetSymbolAddress((void**)&p_W2b, g_W2b);
    cudaGetSymbolAddress((void**)&p_y1, g_y1);
    cudaGetSymbolAddress((void**)&p_y2, g_y2);
    cudaGetSymbolAddress((void**)&p_c, g_c);

    // 0. prep: bf16 packed weights, x, h0
    prep_wc<<<(G4 * KC + 255) / 256, 256>>>(W_hh, W_ih, b_ih, b_hh);
    prep_w12<<<(M1 * HH + M2 * M1 + 255) / 256, 256>>>(W1, W2);
    {
        size_t n = (size_t)TB * OBS + (size_t)BB * HH;
        prep_xh<<<(unsigned)((n + 255) / 256), 256>>>(x, h0);
    }

    // 1. sequential LSTM (tensor-core steps)
    for (int t = 0; t < TT; t++) {
        const bf16* hp = t ? (p_hb + (size_t)(t - 1) * BB * HH) : p_h0b;
        const float* cp = t ? p_c : c0;
        lstm_step_mma<<<dim3(BB / 64, G4 / 128), 256>>>(hp, cp, done + (size_t)t * BB, t);
    }

    // 2. LN stats (LN applied inside mlp1 A-load)
    ln_stats<<<TB / 8, 256>>>();

    // 3. MLP (bf16 mma, ELU fused)
    mlp_mma<HH, M1, true><<<dim3(TB / 64, M1 / 128), 256>>>(p_hb, p_W1b, b1, p_y1, ln_g, ln_b);
    mlp_mma<M1, M2, false><<<dim3(TB / 64, M2 / 128), 256>>>(p_y1, p_W2b, b2, p_y2, nullptr, nullptr);

    // 4. heads
    heads_kernel<<<TB / 16, 384>>>(Wm, bm, Ws, bs, out);
}

// round 4
// speedup vs baseline: 3.4106x; 1.0002x over previous
#include <cuda_runtime.h>
#include <cuda_bf16.h>
#include <math.h>
#include <stdint.h>

#define TT 64
#define BB 2048
#define OBS 48
#define HH 256
#define G4 1024
#define KC 304            // combined K = HH + OBS
#define M1 512
#define M2 256
#define TB (TT*BB)
#define LOG2PI 1.8378770664093453f

typedef __nv_bfloat16 bf16;

// ---------------- scratch (device globals: allocation-free) ----------------
__device__ __align__(16) bf16 g_Wc[G4 * KC];          // combined [Whh|Wih], [n=j*4+g][k]
__device__ float            g_bias[G4];               // b_ih + b_hh, gate-interleaved
__device__ __align__(16) bf16 g_W1b[M1 * HH];         // [n][k]
__device__ __align__(16) bf16 g_W2b[M2 * M1];         // [n][k]
__device__ __align__(16) bf16 g_xb[(size_t)TB * OBS];
__device__ __align__(16) bf16 g_h0b[BB * HH];
__device__ __align__(16) bf16 g_hb[(size_t)TB * HH];  // all h outputs, bf16
__device__ float            g_c[BB * HH];
__device__ float            g_mu[TB];
__device__ float            g_rs[TB];
__device__ __align__(16) bf16 g_y1[(size_t)TB * M1];
__device__ __align__(16) bf16 g_y2[(size_t)TB * M2];

// ---------------- mma helper ----------------
__device__ __forceinline__ void mma16816(float c[4],
    uint32_t a0, uint32_t a1, uint32_t a2, uint32_t a3,
    uint32_t b0, uint32_t b1)
{
    asm volatile(
        "mma.sync.aligned.m16n8k16.row.col.f32.bf16.bf16.f32 "
        "{%0,%1,%2,%3}, {%4,%5,%6,%7}, {%8,%9}, {%0,%1,%2,%3};"
        : "+f"(c[0]), "+f"(c[1]), "+f"(c[2]), "+f"(c[3])
        : "r"(a0), "r"(a1), "r"(a2), "r"(a3), "r"(b0), "r"(b1));
}

__device__ __forceinline__ float sigmoidf_(float x) {
    return 1.0f / (1.0f + __expf(-x));
}

#define AS_STRIDE 24
#define BS_STRIDE 24
#define CS_STRIDE 132

// ---------------- prep kernels ----------------
__global__ void prep_wc(const float* __restrict__ W_hh, const float* __restrict__ W_ih,
                        const float* __restrict__ b_ih, const float* __restrict__ b_hh)
{
    int idx = blockIdx.x * blockDim.x + threadIdx.x;
    if (idx >= G4 * KC) return;
    int n = idx / KC, k = idx % KC;
    int g = n & 3, j = n >> 2;
    float v = (k < HH) ? W_hh[(size_t)(g * HH + j) * HH + k]
                       : W_ih[(size_t)(g * HH + j) * OBS + (k - HH)];
    g_Wc[idx] = __float2bfloat16(v);
    if (k == 0) g_bias[n] = b_ih[g * HH + j] + b_hh[g * HH + j];
}

__global__ void prep_w12(const float* __restrict__ W1, const float* __restrict__ W2)
{
    int idx = blockIdx.x * blockDim.x + threadIdx.x;
    if (idx >= M1 * HH + M2 * M1) return;
    if (idx < M1 * HH) {
        int n = idx / HH, k = idx % HH;     // W1: [HH][M1] -> [n][k]
        g_W1b[idx] = __float2bfloat16(W1[(size_t)k * M1 + n]);
    } else {
        int i = idx - M1 * HH;
        int n = i / M1, k = i % M1;         // W2: [M1][M2] -> [n][k]
        g_W2b[i] = __float2bfloat16(W2[(size_t)k * M2 + n]);
    }
}

__global__ void prep_xh(const float* __restrict__ x, const float* __restrict__ h0)
{
    size_t idx = (size_t)blockIdx.x * blockDim.x + threadIdx.x;
    size_t nx = (size_t)TB * OBS;
    if (idx < nx) g_xb[idx] = __float2bfloat16(x[idx]);
    else if (idx < nx + (size_t)BB * HH) {
        size_t i = idx - nx;
        g_h0b[i] = __float2bfloat16(h0[i]);
    }
}

// ---------------- LSTM step (bf16 mma) ----------------
// C[64 x 128] tile of gates = A[64 x 304] x B[304 x 128]
// A = [h*keep | x_t] bf16, B = gate-interleaved combined weights.
__global__ __launch_bounds__(256) void lstm_step_mma(
    const bf16* __restrict__ hprev, const float* __restrict__ cprev,
    const int* __restrict__ done_t, int t)
{
    __shared__ bf16  as[64 * AS_STRIDE];
    __shared__ bf16  bs[128 * BS_STRIDE];
    __shared__ float csm[64 * CS_STRIDE];
    __shared__ float bias_s[128];

    const int tid = threadIdx.x;
    const int b0 = blockIdx.x * 64;
    const int n0 = blockIdx.y * 128;
    const bf16* xb_t = g_xb + (size_t)t * BB * OBS;

    if (tid < 128) bias_s[tid] = g_bias[n0 + tid];

    // A loader: each thread fills 4 bf16 of one row per chunk
    const int arow = tid >> 2;
    const int aseg = tid & 3;
    const int keepA = 1 - done_t[b0 + arow];
    const bf16* hrow = hprev + (size_t)(b0 + arow) * HH + aseg * 4;
    const bf16* xrow = xb_t + (size_t)(b0 + arow) * OBS + aseg * 4;
    // B loader: each thread fills 8 bf16 of one n-row per chunk
    const int bn = tid >> 1;
    const int bh = tid & 1;
    const bf16* wrow = g_Wc + (size_t)(n0 + bn) * KC + bh * 8;

    const int lane = tid & 31;
    const int warp = tid >> 5;
    const int wm = warp & 1, wn = warp >> 1;    // 2 x 4 warp grid
    const int g8 = lane >> 2, t4 = lane & 3;

    float acc[2][4][4];
#pragma unroll
    for (int i = 0; i < 2; i++)
#pragma unroll
        for (int j = 0; j < 4; j++)
#pragma unroll
            for (int k = 0; k < 4; k++) acc[i][j][k] = 0.0f;

    // prefetch chunk 0
    uint2 aReg;
    uint4 bReg;
    {
        aReg = *(const uint2*)hrow;           // kt = 0 (< HH)
        if (!keepA) { aReg.x = 0u; aReg.y = 0u; }
        bReg = *(const uint4*)wrow;
    }

#pragma unroll 1
    for (int ch = 0; ch < KC / 16; ch++) {
        __syncthreads();
        *(uint2*)&as[arow * AS_STRIDE + aseg * 4] = aReg;
        *(uint4*)&bs[bn * BS_STRIDE + bh * 8]    = bReg;
        __syncthreads();

        if (ch < KC / 16 - 1) {
            int kt = (ch + 1) * 16;
            if (kt < HH) {
                aReg = *(const uint2*)(hrow + kt);
                if (!keepA) { aReg.x = 0u; aReg.y = 0u; }
            } else {
                aReg = *(const uint2*)(xrow + (kt - HH));
            }
            bReg = *(const uint4*)(wrow + kt);
        }

        uint32_t af[2][4];
#pragma unroll
        for (int am = 0; am < 2; am++) {
            const bf16* ap = &as[(wm * 32 + am * 16 + g8) * AS_STRIDE + t4 * 2];
            af[am][0] = *(const uint32_t*)ap;
            af[am][1] = *(const uint32_t*)(ap + 8 * AS_STRIDE);
            af[am][2] = *(const uint32_t*)(ap + 8);
            af[am][3] = *(const uint32_t*)(ap + 8 * AS_STRIDE + 8);
        }
#pragma unroll
        for (int an = 0; an < 4; an++) {
            const bf16* bp = &bs[(wn * 32 + an * 8 + g8) * BS_STRIDE + t4 * 2];
            uint32_t b0v = *(const uint32_t*)bp;
            uint32_t b1v = *(const uint32_t*)(bp + 8);
#pragma unroll
            for (int am = 0; am < 2; am++)
                mma16816(acc[am][an], af[am][0], af[am][1], af[am][2], af[am][3], b0v, b1v);
        }
    }

    // C -> smem
#pragma unroll
    for (int am = 0; am < 2; am++)
#pragma unroll
        for (int an = 0; an < 4; an++) {
            int r = wm * 32 + am * 16 + g8;
            int c = wn * 32 + an * 8 + t4 * 2;
            *(float2*)&csm[r * CS_STRIDE + c]       = make_float2(acc[am][an][0], acc[am][an][1]);
            *(float2*)&csm[(r + 8) * CS_STRIDE + c] = make_float2(acc[am][an][2], acc[am][an][3]);
        }
    __syncthreads();

    // gate fusion epilogue: 64 rows x 32 j per block
    bf16* hout = g_hb + (size_t)t * BB * HH;
    const int j0 = n0 >> 2;
#pragma unroll
    for (int i = 0; i < 8; i++) {
        int p = i * 256 + tid;
        int bl = p >> 5, jl = p & 31;
        float4 gq = *(const float4*)&csm[bl * CS_STRIDE + jl * 4];
        float gi = gq.x + bias_s[jl * 4 + 0];
        float gf = gq.y + bias_s[jl * 4 + 1];
        float gg = gq.z + bias_s[jl * 4 + 2];
        float go = gq.w + bias_s[jl * 4 + 3];
        int b = b0 + bl;
        int j = j0 + jl;
        float kb = 1.0f - (float)done_t[b];
        float cold = cprev[b * HH + j] * kb;
        float cn = sigmoidf_(gf) * cold + sigmoidf_(gi) * tanhf(gg);
        float hn = sigmoidf_(go) * tanhf(cn);
        g_c[b * HH + j] = cn;
        hout[(size_t)b * HH + j] = __float2bfloat16(hn);
    }
}

// ---------------- LayerNorm stats (per row of g_hb) ----------------
__global__ __launch_bounds__(256) void ln_stats()
{
    int row = blockIdx.x * 8 + (threadIdx.x >> 5);
    int lane = threadIdx.x & 31;
    uint4 u = *(const uint4*)(g_hb + (size_t)row * HH + lane * 8);
    const __nv_bfloat162* p = (const __nv_bfloat162*)&u;
    float s = 0.0f, s2 = 0.0f;
#pragma unroll
    for (int i = 0; i < 4; i++) {
        float2 f = __bfloat1622float2(p[i]);
        s += f.x + f.y;
        s2 += f.x * f.x + f.y * f.y;
    }
#pragma unroll
    for (int o = 16; o; o >>= 1) {
        s  += __shfl_xor_sync(0xffffffffu, s, o);
        s2 += __shfl_xor_sync(0xffffffffu, s2, o);
    }
    if (lane == 0) {
        float mu = s * (1.0f / HH);
        float var = s2 * (1.0f / HH) - mu * mu;
        g_mu[row] = mu;
        g_rs[row] = rsqrtf(var + 1e-5f);
    }
}

// ---------------- MLP GEMM (bf16 mma): Out = ELU(A @ B^T + bias) ----------------
// A rows optionally LayerNorm-transformed on load. B stored [n][k].
template <int KD, int ND, bool LNA>
__global__ __launch_bounds__(256) void mlp_mma(
    const bf16* __restrict__ A, const bf16* __restrict__ Bw,
    const float* __restrict__ bias, bf16* __restrict__ Out,
    const float* __restrict__ gamma, const float* __restrict__ beta)
{
    __shared__ bf16 as[64 * AS_STRIDE];
    __shared__ bf16 bs[128 * BS_STRIDE];

    const int tid = threadIdx.x;
    const size_t m0 = (size_t)blockIdx.x * 64;
    const int n0 = blockIdx.y * 128;

    const int arow = tid >> 2;
    const int aseg = tid & 3;
    const bf16* arp = A + (m0 + arow) * KD + aseg * 4;
    float mur = 0.0f, rsr = 0.0f;
    if (LNA) { mur = g_mu[m0 + arow]; rsr = g_rs[m0 + arow]; }

    const int bn = tid >> 1;
    const int bh = tid & 1;
    const bf16* wrow = Bw + (size_t)(n0 + bn) * KD + bh * 8;

    const int lane = tid & 31;
    const int warp = tid >> 5;
    const int wm = warp & 1, wn = warp >> 1;
    const int g8 = lane >> 2, t4 = lane & 3;

    float acc[2][4][4];
#pragma unroll
    for (int i = 0; i < 2; i++)
#pragma unroll
        for (int j = 0; j < 4; j++)
#pragma unroll
            for (int k = 0; k < 4; k++) acc[i][j][k] = 0.0f;

    uint2 aReg;
    uint4 bReg;

    auto loadA = [&](int kt) {
        uint2 v = *(const uint2*)(arp + kt);
        if (LNA) {
            __nv_bfloat162* vp = (__nv_bfloat162*)&v;
            int kb = kt + aseg * 4;
            float2 f0 = __bfloat1622float2(vp[0]);
            float2 f1 = __bfloat1622float2(vp[1]);
            f0.x = (f0.x - mur) * rsr * __ldg(&gamma[kb + 0]) + __ldg(&beta[kb + 0]);
            f0.y = (f0.y - mur) * rsr * __ldg(&gamma[kb + 1]) + __ldg(&beta[kb + 1]);
            f1.x = (f1.x - mur) * rsr * __ldg(&gamma[kb + 2]) + __ldg(&beta[kb + 2]);
            f1.y = (f1.y - mur) * rsr * __ldg(&gamma[kb + 3]) + __ldg(&beta[kb + 3]);
            vp[0] = __floats2bfloat162_rn(f0.x, f0.y);
            vp[1] = __floats2bfloat162_rn(f1.x, f1.y);
        }
        aReg = v;
    };

    loadA(0);
    bReg = *(const uint4*)wrow;

#pragma unroll 1
    for (int ch = 0; ch < KD / 16; ch++) {
        __syncthreads();
        *(uint2*)&as[arow * AS_STRIDE + aseg * 4] = aReg;
        *(uint4*)&bs[bn * BS_STRIDE + bh * 8]    = bReg;
        __syncthreads();

        if (ch < KD / 16 - 1) {
            loadA((ch + 1) * 16);
            bReg = *(const uint4*)(wrow + (ch + 1) * 16);
        }

        uint32_t af[2][4];
#pragma unroll
        for (int am = 0; am < 2; am++) {
            const bf16* ap = &as[(wm * 32 + am * 16 + g8) * AS_STRIDE + t4 * 2];
            af[am][0] = *(const uint32_t*)ap;
            af[am][1] = *(const uint32_t*)(ap + 8 * AS_STRIDE);
            af[am][2] = *(const uint32_t*)(ap + 8);
            af[am][3] = *(const uint32_t*)(ap + 8 * AS_STRIDE + 8);
        }
#pragma unroll
        for (int an = 0; an < 4; an++) {
            const bf16* bp = &bs[(wn * 32 + an * 8 + g8) * BS_STRIDE + t4 * 2];
            uint32_t b0v = *(const uint32_t*)bp;
            uint32_t b1v = *(const uint32_t*)(bp + 8);
#pragma unroll
            for (int am = 0; am < 2; am++)
                mma16816(acc[am][an], af[am][0], af[am][1], af[am][2], af[am][3], b0v, b1v);
        }
    }

    // epilogue: bias + ELU + pack bf16, direct to global
#pragma unroll
    for (int am = 0; am < 2; am++)
#pragma unroll
        for (int an = 0; an < 4; an++) {
            size_t r = m0 + wm * 32 + am * 16 + g8;
            int c = n0 + wn * 32 + an * 8 + t4 * 2;
            float bc0 = __ldg(&bias[c]), bc1 = __ldg(&bias[c + 1]);
            float v0 = acc[am][an][0] + bc0;
            float v1 = acc[am][an][1] + bc1;
            v0 = (v0 > 0.0f) ? v0 : expm1f(v0);
            v1 = (v1 > 0.0f) ? v1 : expm1f(v1);
            *(__nv_bfloat162*)(Out + r * ND + c) = __floats2bfloat162_rn(v0, v1);
            float v2 = acc[am][an][2] + bc0;
            float v3 = acc[am][an][3] + bc1;
            v2 = (v2 > 0.0f) ? v2 : expm1f(v2);
            v3 = (v3 > 0.0f) ? v3 : expm1f(v3);
            *(__nv_bfloat162*)(Out + (r + 8) * ND + c) = __floats2bfloat162_rn(v2, v3);
        }
}

// ---------------- heads: mean, logp, entropy ----------------
__global__ __launch_bounds__(384) void heads_kernel(
    const float* __restrict__ Wm, const float* __restrict__ bm,
    const float* __restrict__ Ws, const float* __restrict__ bs,
    float* __restrict__ out)
{
    __shared__ float wc[M2][24];
    __shared__ float ys[16][M2 + 1];
    __shared__ float ls[16][12];
    int tid = threadIdx.x;
    for (int i = tid; i < M2 * 12; i += 384) {
        int k = i / 12, o = i % 12;
        wc[k][o] = Wm[i];
        wc[k][o + 12] = Ws[i];
    }
    int n0 = blockIdx.x * 16;
    for (int i = tid; i < 16 * 32; i += 384) {
        int r = i >> 5, seg = i & 31;
        uint4 u = *(const uint4*)(g_y2 + (size_t)(n0 + r) * M2 + seg * 8);
        const __nv_bfloat162* p = (const __nv_bfloat162*)&u;
#pragma unroll
        for (int q = 0; q < 4; q++) {
            float2 f = __bfloat1622float2(p[q]);
            ys[r][seg * 8 + 2 * q]     = f.x;
            ys[r][seg * 8 + 2 * q + 1] = f.y;
        }
    }
    __syncthreads();
    int r = tid / 24, o = tid % 24;
    float acc = 0.0f;
#pragma unroll 8
    for (int k = 0; k < M2; k++) acc += ys[r][k] * wc[k][o];
    if (o < 12) {
        out[(size_t)(n0 + r) * 14 + o] = acc + bm[o];
    } else {
        float l = acc + bs[o - 12];
        l = fminf(fmaxf(l, -5.0f), 2.0f);
        ls[r][o - 12] = l;
    }
    __syncthreads();
    if (o == 0) {
        float S = 0.0f;
#pragma unroll
        for (int i = 0; i < 12; i++) S += ls[r][i];
        out[(size_t)(n0 + r) * 14 + 12] = -S - 6.0f * LOG2PI;
        out[(size_t)(n0 + r) * 14 + 13] = S + 6.0f + 6.0f * LOG2PI;
    }
}

// ---------------- launch ----------------
extern "C" void kernel_launch(void* const* d_in, const int* in_sizes, int n_in,
                              void* d_out, int out_size)
{
    const float *x, *h0, *c0, *W_ih, *W_hh, *b_ih, *b_hh, *ln_g, *ln_b;
    const float *W1, *b1, *W2, *b2, *Wm, *bm, *Ws, *bs;
    const int* done;

    if (in_sizes[1] == TT * BB) {
        // setup_inputs dict order
        x = (const float*)d_in[0];  done = (const int*)d_in[1];
        h0 = (const float*)d_in[2]; c0 = (const float*)d_in[3];
        W_ih = (const float*)d_in[4]; W_hh = (const float*)d_in[5];
        b_ih = (const float*)d_in[6]; b_hh = (const float*)d_in[7];
        ln_g = (const float*)d_in[8]; ln_b = (const float*)d_in[9];
        W1 = (const float*)d_in[10]; b1 = (const float*)d_in[11];
        W2 = (const float*)d_in[12]; b2 = (const float*)d_in[13];
        Wm = (const float*)d_in[14]; bm = (const float*)d_in[15];
        Ws = (const float*)d_in[16]; bs = (const float*)d_in[17];
    } else {
        // reference() signature order
        x = (const float*)d_in[0];
        h0 = (const float*)d_in[1]; c0 = (const float*)d_in[2];
        W_ih = (const float*)d_in[3]; W_hh = (const float*)d_in[4];
        b_ih = (const float*)d_in[5]; b_hh = (const float*)d_in[6];
        ln_g = (const float*)d_in[7]; ln_b = (const float*)d_in[8];
        W1 = (const float*)d_in[9];  b1 = (const float*)d_in[10];
        W2 = (const float*)d_in[11]; b2 = (const float*)d_in[12];
        Wm = (const float*)d_in[13]; bm = (const float*)d_in[14];
        Ws = (const float*)d_in[15]; bs = (const float*)d_in[16];
        done = (const int*)d_in[17];
    }

    float* out = (float*)d_out;

    bf16 *p_hb, *p_h0b, *p_W1b, *p_W2b, *p_y1, *p_y2;
    float* p_c;
    cudaGetSymbolAddress((void**)&p_hb, g_hb);
    cudaGetSymbolAddress((void**)&p_h0b, g_h0b);
    cudaGetSymbolAddress((void**)&p_W1b, g_W1b);
    cudaGetSymbolAddress((void**)&p_W2b, g_W2b);
    cudaGetSymbolAddress((void**)&p_y1, g_y1);
    cudaGetSymbolAddress((void**)&p_y2, g_y2);
    cudaGetSymbolAddress((void**)&p_c, g_c);

    // 0. prep: bf16 packed weights, x, h0
    prep_wc<<<(G4 * KC + 255) / 256, 256>>>(W_hh, W_ih, b_ih, b_hh);
    prep_w12<<<(M1 * HH + M2 * M1 + 255) / 256, 256>>>(W1, W2);
    {
        size_t n = (size_t)TB * OBS + (size_t)BB * HH;
        prep_xh<<<(unsigned)((n + 255) / 256), 256>>>(x, h0);
    }

    // 1. sequential LSTM (tensor-core steps)
    for (int t = 0; t < TT; t++) {
        const bf16* hp = t ? (p_hb + (size_t)(t - 1) * BB * HH) : p_h0b;
        const float* cp = t ? p_c : c0;
        lstm_step_mma<<<dim3(BB / 64, G4 / 128), 256>>>(hp, cp, done + (size_t)t * BB, t);
    }

    // 2. LN stats (LN applied inside mlp1 A-load)
    ln_stats<<<TB / 8, 256>>>();

    // 3. MLP (bf16 mma, ELU fused)
    mlp_mma<HH, M1, true><<<dim3(TB / 64, M1 / 128), 256>>>(p_hb, p_W1b, b1, p_y1, ln_g, ln_b);
    mlp_mma<M1, M2, false><<<dim3(TB / 64, M2 / 128), 256>>>(p_y1, p_W2b, b2, p_y2, nullptr, nullptr);

    // 4. heads
    heads_kernel<<<TB / 16, 384>>>(Wm, bm, Ws, bs, out);
}

// round 5
// speedup vs baseline: 3.4381x; 1.0081x over previous
#include <cuda_runtime.h>
#include <cuda_bf16.h>
#include <math.h>
#include <stdint.h>

#define TT 64
#define BB 2048
#define OBS 48
#define HH 256
#define G4 1024
#define KC 304            // combined K = HH + OBS
#define M1 512
#define M2 256
#define TB (TT*BB)
#define LOG2PI 1.8378770664093453f

typedef __nv_bfloat16 bf16;

// ---------------- scratch (device globals: allocation-free) ----------------
__device__ __align__(16) bf16 g_Wc[G4 * KC];          // combined [Whh|Wih], [n=j*4+g][k]
__device__ float            g_bias[G4];               // b_ih + b_hh, gate-interleaved
__device__ __align__(16) bf16 g_W1b[M1 * HH];         // [n][k]
__device__ __align__(16) bf16 g_W2b[M2 * M1];         // [n][k]
__device__ __align__(16) bf16 g_xb[(size_t)TB * OBS];
__device__ __align__(16) bf16 g_h0b[BB * HH];
__device__ __align__(16) bf16 g_hb[(size_t)TB * HH];  // all h outputs, bf16
__device__ float            g_c[BB * HH];
__device__ float            g_mu[TB];
__device__ float            g_rs[TB];
__device__ __align__(16) bf16 g_y1[(size_t)TB * M1];
__device__ __align__(16) bf16 g_y2[(size_t)TB * M2];

// ---------------- mma helper ----------------
__device__ __forceinline__ void mma16816(float c[4],
    uint32_t a0, uint32_t a1, uint32_t a2, uint32_t a3,
    uint32_t b0, uint32_t b1)
{
    asm volatile(
        "mma.sync.aligned.m16n8k16.row.col.f32.bf16.bf16.f32 "
        "{%0,%1,%2,%3}, {%4,%5,%6,%7}, {%8,%9}, {%0,%1,%2,%3};"
        : "+f"(c[0]), "+f"(c[1]), "+f"(c[2]), "+f"(c[3])
        : "r"(a0), "r"(a1), "r"(a2), "r"(a3), "r"(b0), "r"(b1));
}

__device__ __forceinline__ float sigmoidf_(float x) {
    return 1.0f / (1.0f + __expf(-x));
}

#define AS_STRIDE 24
#define BS_STRIDE 24
#define CS_STRIDE 132

// ---------------- prep kernels ----------------
__global__ void prep_wc(const float* __restrict__ W_hh, const float* __restrict__ W_ih,
                        const float* __restrict__ b_ih, const float* __restrict__ b_hh)
{
    int idx = blockIdx.x * blockDim.x + threadIdx.x;
    if (idx >= G4 * KC) return;
    int n = idx / KC, k = idx % KC;
    int g = n & 3, j = n >> 2;
    float v = (k < HH) ? W_hh[(size_t)(g * HH + j) * HH + k]
                       : W_ih[(size_t)(g * HH + j) * OBS + (k - HH)];
    g_Wc[idx] = __float2bfloat16(v);
    if (k == 0) g_bias[n] = b_ih[g * HH + j] + b_hh[g * HH + j];
}

__global__ void prep_w12(const float* __restrict__ W1, const float* __restrict__ W2)
{
    int idx = blockIdx.x * blockDim.x + threadIdx.x;
    if (idx >= M1 * HH + M2 * M1) return;
    if (idx < M1 * HH) {
        int n = idx / HH, k = idx % HH;     // W1: [HH][M1] -> [n][k]
        g_W1b[idx] = __float2bfloat16(W1[(size_t)k * M1 + n]);
    } else {
        int i = idx - M1 * HH;
        int n = i / M1, k = i % M1;         // W2: [M1][M2] -> [n][k]
        g_W2b[i] = __float2bfloat16(W2[(size_t)k * M2 + n]);
    }
}

__global__ void prep_xh(const float* __restrict__ x, const float* __restrict__ h0)
{
    size_t idx = (size_t)blockIdx.x * blockDim.x + threadIdx.x;
    size_t nx = (size_t)TB * OBS;
    if (idx < nx) g_xb[idx] = __float2bfloat16(x[idx]);
    else if (idx < nx + (size_t)BB * HH) {
        size_t i = idx - nx;
        g_h0b[i] = __float2bfloat16(h0[i]);
    }
}

// ---------------- LSTM step (bf16 mma) ----------------
// C[64 x 128] tile of gates = A[64 x 304] x B[304 x 128]
// A = [h*keep | x_t] bf16, B = gate-interleaved combined weights.
__global__ __launch_bounds__(256) void lstm_step_mma(
    const bf16* __restrict__ hprev, const float* __restrict__ cprev,
    const int* __restrict__ done_t, int t)
{
    __shared__ bf16  as[64 * AS_STRIDE];
    __shared__ bf16  bs[128 * BS_STRIDE];
    __shared__ float csm[64 * CS_STRIDE];
    __shared__ float bias_s[128];

    const int tid = threadIdx.x;
    const int b0 = blockIdx.x * 64;
    const int n0 = blockIdx.y * 128;
    const bf16* xb_t = g_xb + (size_t)t * BB * OBS;

    if (tid < 128) bias_s[tid] = g_bias[n0 + tid];

    // A loader: each thread fills 4 bf16 of one row per chunk
    const int arow = tid >> 2;
    const int aseg = tid & 3;
    const int keepA = 1 - done_t[b0 + arow];
    const bf16* hrow = hprev + (size_t)(b0 + arow) * HH + aseg * 4;
    const bf16* xrow = xb_t + (size_t)(b0 + arow) * OBS + aseg * 4;
    // B loader: each thread fills 8 bf16 of one n-row per chunk
    const int bn = tid >> 1;
    const int bh = tid & 1;
    const bf16* wrow = g_Wc + (size_t)(n0 + bn) * KC + bh * 8;

    const int lane = tid & 31;
    const int warp = tid >> 5;
    const int wm = warp & 1, wn = warp >> 1;    // 2 x 4 warp grid
    const int g8 = lane >> 2, t4 = lane & 3;

    float acc[2][4][4];
#pragma unroll
    for (int i = 0; i < 2; i++)
#pragma unroll
        for (int j = 0; j < 4; j++)
#pragma unroll
            for (int k = 0; k < 4; k++) acc[i][j][k] = 0.0f;

    // prefetch chunk 0
    uint2 aReg;
    uint4 bReg;
    {
        aReg = *(const uint2*)hrow;           // kt = 0 (< HH)
        if (!keepA) { aReg.x = 0u; aReg.y = 0u; }
        bReg = *(const uint4*)wrow;
    }

#pragma unroll 1
    for (int ch = 0; ch < KC / 16; ch++) {
        __syncthreads();
        *(uint2*)&as[arow * AS_STRIDE + aseg * 4] = aReg;
        *(uint4*)&bs[bn * BS_STRIDE + bh * 8]    = bReg;
        __syncthreads();

        if (ch < KC / 16 - 1) {
            int kt = (ch + 1) * 16;
            if (kt < HH) {
                aReg = *(const uint2*)(hrow + kt);
                if (!keepA) { aReg.x = 0u; aReg.y = 0u; }
            } else {
                aReg = *(const uint2*)(xrow + (kt - HH));
            }
            bReg = *(const uint4*)(wrow + kt);
        }

        uint32_t af[2][4];
#pragma unroll
        for (int am = 0; am < 2; am++) {
            const bf16* ap = &as[(wm * 32 + am * 16 + g8) * AS_STRIDE + t4 * 2];
            af[am][0] = *(const uint32_t*)ap;
            af[am][1] = *(const uint32_t*)(ap + 8 * AS_STRIDE);
            af[am][2] = *(const uint32_t*)(ap + 8);
            af[am][3] = *(const uint32_t*)(ap + 8 * AS_STRIDE + 8);
        }
#pragma unroll
        for (int an = 0; an < 4; an++) {
            const bf16* bp = &bs[(wn * 32 + an * 8 + g8) * BS_STRIDE + t4 * 2];
            uint32_t b0v = *(const uint32_t*)bp;
            uint32_t b1v = *(const uint32_t*)(bp + 8);
#pragma unroll
            for (int am = 0; am < 2; am++)
                mma16816(acc[am][an], af[am][0], af[am][1], af[am][2], af[am][3], b0v, b1v);
        }
    }

    // C -> smem
#pragma unroll
    for (int am = 0; am < 2; am++)
#pragma unroll
        for (int an = 0; an < 4; an++) {
            int r = wm * 32 + am * 16 + g8;
            int c = wn * 32 + an * 8 + t4 * 2;
            *(float2*)&csm[r * CS_STRIDE + c]       = make_float2(acc[am][an][0], acc[am][an][1]);
            *(float2*)&csm[(r + 8) * CS_STRIDE + c] = make_float2(acc[am][an][2], acc[am][an][3]);
        }
    __syncthreads();

    // gate fusion epilogue: 64 rows x 32 j per block
    bf16* hout = g_hb + (size_t)t * BB * HH;
    const int j0 = n0 >> 2;
#pragma unroll
    for (int i = 0; i < 8; i++) {
        int p = i * 256 + tid;
        int bl = p >> 5, jl = p & 31;
        float4 gq = *(const float4*)&csm[bl * CS_STRIDE + jl * 4];
        float gi = gq.x + bias_s[jl * 4 + 0];
        float gf = gq.y + bias_s[jl * 4 + 1];
        float gg = gq.z + bias_s[jl * 4 + 2];
        float go = gq.w + bias_s[jl * 4 + 3];
        int b = b0 + bl;
        int j = j0 + jl;
        float kb = 1.0f - (float)done_t[b];
        float cold = cprev[b * HH + j] * kb;
        float cn = sigmoidf_(gf) * cold + sigmoidf_(gi) * tanhf(gg);
        float hn = sigmoidf_(go) * tanhf(cn);
        g_c[b * HH + j] = cn;
        hout[(size_t)b * HH + j] = __float2bfloat16(hn);
    }
}

// ---------------- LayerNorm stats (per row of g_hb) ----------------
__global__ __launch_bounds__(256) void ln_stats()
{
    int row = blockIdx.x * 8 + (threadIdx.x >> 5);
    int lane = threadIdx.x & 31;
    uint4 u = *(const uint4*)(g_hb + (size_t)row * HH + lane * 8);
    const __nv_bfloat162* p = (const __nv_bfloat162*)&u;
    float s = 0.0f, s2 = 0.0f;
#pragma unroll
    for (int i = 0; i < 4; i++) {
        float2 f = __bfloat1622float2(p[i]);
        s += f.x + f.y;
        s2 += f.x * f.x + f.y * f.y;
    }
#pragma unroll
    for (int o = 16; o; o >>= 1) {
        s  += __shfl_xor_sync(0xffffffffu, s, o);
        s2 += __shfl_xor_sync(0xffffffffu, s2, o);
    }
    if (lane == 0) {
        float mu = s * (1.0f / HH);
        float var = s2 * (1.0f / HH) - mu * mu;
        g_mu[row] = mu;
        g_rs[row] = rsqrtf(var + 1e-5f);
    }
}

// ---------------- MLP GEMM (bf16 mma): Out = ELU(A @ B^T + bias) ----------------
// A rows optionally LayerNorm-transformed on load. B stored [n][k].
template <int KD, int ND, bool LNA>
__global__ __launch_bounds__(256) void mlp_mma(
    const bf16* __restrict__ A, const bf16* __restrict__ Bw,
    const float* __restrict__ bias, bf16* __restrict__ Out,
    const float* __restrict__ gamma, const float* __restrict__ beta)
{
    __shared__ bf16 as[64 * AS_STRIDE];
    __shared__ bf16 bs[128 * BS_STRIDE];

    const int tid = threadIdx.x;
    const size_t m0 = (size_t)blockIdx.x * 64;
    const int n0 = blockIdx.y * 128;

    const int arow = tid >> 2;
    const int aseg = tid & 3;
    const bf16* arp = A + (m0 + arow) * KD + aseg * 4;
    float mur = 0.0f, rsr = 0.0f;
    if (LNA) { mur = g_mu[m0 + arow]; rsr = g_rs[m0 + arow]; }

    const int bn = tid >> 1;
    const int bh = tid & 1;
    const bf16* wrow = Bw + (size_t)(n0 + bn) * KD + bh * 8;

    const int lane = tid & 31;
    const int warp = tid >> 5;
    const int wm = warp & 1, wn = warp >> 1;
    const int g8 = lane >> 2, t4 = lane & 3;

    float acc[2][4][4];
#pragma unroll
    for (int i = 0; i < 2; i++)
#pragma unroll
        for (int j = 0; j < 4; j++)
#pragma unroll
            for (int k = 0; k < 4; k++) acc[i][j][k] = 0.0f;

    uint2 aReg;
    uint4 bReg;

    auto loadA = [&](int kt) {
        uint2 v = *(const uint2*)(arp + kt);
        if (LNA) {
            __nv_bfloat162* vp = (__nv_bfloat162*)&v;
            int kb = kt + aseg * 4;
            float2 f0 = __bfloat1622float2(vp[0]);
            float2 f1 = __bfloat1622float2(vp[1]);
            f0.x = (f0.x - mur) * rsr * __ldg(&gamma[kb + 0]) + __ldg(&beta[kb + 0]);
            f0.y = (f0.y - mur) * rsr * __ldg(&gamma[kb + 1]) + __ldg(&beta[kb + 1]);
            f1.x = (f1.x - mur) * rsr * __ldg(&gamma[kb + 2]) + __ldg(&beta[kb + 2]);
            f1.y = (f1.y - mur) * rsr * __ldg(&gamma[kb + 3]) + __ldg(&beta[kb + 3]);
            vp[0] = __floats2bfloat162_rn(f0.x, f0.y);
            vp[1] = __floats2bfloat162_rn(f1.x, f1.y);
        }
        aReg = v;
    };

    loadA(0);
    bReg = *(const uint4*)wrow;

#pragma unroll 1
    for (int ch = 0; ch < KD / 16; ch++) {
        __syncthreads();
        *(uint2*)&as[arow * AS_STRIDE + aseg * 4] = aReg;
        *(uint4*)&bs[bn * BS_STRIDE + bh * 8]    = bReg;
        __syncthreads();

        if (ch < KD / 16 - 1) {
            loadA((ch + 1) * 16);
            bReg = *(const uint4*)(wrow + (ch + 1) * 16);
        }

        uint32_t af[2][4];
#pragma unroll
        for (int am = 0; am < 2; am++) {
            const bf16* ap = &as[(wm * 32 + am * 16 + g8) * AS_STRIDE + t4 * 2];
            af[am][0] = *(const uint32_t*)ap;
            af[am][1] = *(const uint32_t*)(ap + 8 * AS_STRIDE);
            af[am][2] = *(const uint32_t*)(ap + 8);
            af[am][3] = *(const uint32_t*)(ap + 8 * AS_STRIDE + 8);
        }
#pragma unroll
        for (int an = 0; an < 4; an++) {
            const bf16* bp = &bs[(wn * 32 + an * 8 + g8) * BS_STRIDE + t4 * 2];
            uint32_t b0v = *(const uint32_t*)bp;
            uint32_t b1v = *(const uint32_t*)(bp + 8);
#pragma unroll
            for (int am = 0; am < 2; am++)
                mma16816(acc[am][an], af[am][0], af[am][1], af[am][2], af[am][3], b0v, b1v);
        }
    }

    // epilogue: bias + ELU + pack bf16, direct to global
#pragma unroll
    for (int am = 0; am < 2; am++)
#pragma unroll
        for (int an = 0; an < 4; an++) {
            size_t r = m0 + wm * 32 + am * 16 + g8;
            int c = n0 + wn * 32 + an * 8 + t4 * 2;
            float bc0 = __ldg(&bias[c]), bc1 = __ldg(&bias[c + 1]);
            float v0 = acc[am][an][0] + bc0;
            float v1 = acc[am][an][1] + bc1;
            v0 = (v0 > 0.0f) ? v0 : expm1f(v0);
            v1 = (v1 > 0.0f) ? v1 : expm1f(v1);
            *(__nv_bfloat162*)(Out + r * ND + c) = __floats2bfloat162_rn(v0, v1);
            float v2 = acc[am][an][2] + bc0;
            float v3 = acc[am][an][3] + bc1;
            v2 = (v2 > 0.0f) ? v2 : expm1f(v2);
            v3 = (v3 > 0.0f) ? v3 : expm1f(v3);
            *(__nv_bfloat162*)(Out + (r + 8) * ND + c) = __floats2bfloat162_rn(v2, v3);
        }
}

// ---------------- heads: mean, logp, entropy ----------------
__global__ __launch_bounds__(384) void heads_kernel(
    const float* __restrict__ Wm, const float* __restrict__ bm,
    const float* __restrict__ Ws, const float* __restrict__ bs,
    float* __restrict__ out)
{
    __shared__ float wc[M2][24];
    __shared__ float ys[16][M2 + 1];
    __shared__ float ls[16][12];
    int tid = threadIdx.x;
    for (int i = tid; i < M2 * 12; i += 384) {
        int k = i / 12, o = i % 12;
        wc[k][o] = Wm[i];
        wc[k][o + 12] = Ws[i];
    }
    int n0 = blockIdx.x * 16;
    for (int i = tid; i < 16 * 32; i += 384) {
        int r = i >> 5, seg = i & 31;
        uint4 u = *(const uint4*)(g_y2 + (size_t)(n0 + r) * M2 + seg * 8);
        const __nv_bfloat162* p = (const __nv_bfloat162*)&u;
#pragma unroll
        for (int q = 0; q < 4; q++) {
            float2 f = __bfloat1622float2(p[q]);
            ys[r][seg * 8 + 2 * q]     = f.x;
            ys[r][seg * 8 + 2 * q + 1] = f.y;
        }
    }
    __syncthreads();
    int r = tid / 24, o = tid % 24;
    float acc = 0.0f;
#pragma unroll 8
    for (int k = 0; k < M2; k++) acc += ys[r][k] * wc[k][o];
    if (o < 12) {
        out[(size_t)(n0 + r) * 14 + o] = acc + bm[o];
    } else {
        float l = acc + bs[o - 12];
        l = fminf(fmaxf(l, -5.0f), 2.0f);
        ls[r][o - 12] = l;
    }
    __syncthreads();
    if (o == 0) {
        float S = 0.0f;
#pragma unroll
        for (int i = 0; i < 12; i++) S += ls[r][i];
        out[(size_t)(n0 + r) * 14 + 12] = -S - 6.0f * LOG2PI;
        out[(size_t)(n0 + r) * 14 + 13] = S + 6.0f + 6.0f * LOG2PI;
    }
}

// ---------------- launch ----------------
extern "C" void kernel_launch(void* const* d_in, const int* in_sizes, int n_in,
                              void* d_out, int out_size)
{
    const float *x, *h0, *c0, *W_ih, *W_hh, *b_ih, *b_hh, *ln_g, *ln_b;
    const float *W1, *b1, *W2, *b2, *Wm, *bm, *Ws, *bs;
    const int* done;

    if (in_sizes[1] == TT * BB) {
        // setup_inputs dict order
        x = (const float*)d_in[0];  done = (const int*)d_in[1];
        h0 = (const float*)d_in[2]; c0 = (const float*)d_in[3];
        W_ih = (const float*)d_in[4]; W_hh = (const float*)d_in[5];
        b_ih = (const float*)d_in[6]; b_hh = (const float*)d_in[7];
        ln_g = (const float*)d_in[8]; ln_b = (const float*)d_in[9];
        W1 = (const float*)d_in[10]; b1 = (const float*)d_in[11];
        W2 = (const float*)d_in[12]; b2 = (const float*)d_in[13];
        Wm = (const float*)d_in[14]; bm = (const float*)d_in[15];
        Ws = (const float*)d_in[16]; bs = (const float*)d_in[17];
    } else {
        // reference() signature order
        x = (const float*)d_in[0];
        h0 = (const float*)d_in[1]; c0 = (const float*)d_in[2];
        W_ih = (const float*)d_in[3]; W_hh = (const float*)d_in[4];
        b_ih = (const float*)d_in[5]; b_hh = (const float*)d_in[6];
        ln_g = (const float*)d_in[7]; ln_b = (const float*)d_in[8];
        W1 = (const float*)d_in[9];  b1 = (const float*)d_in[10];
        W2 = (const float*)d_in[11]; b2 = (const float*)d_in[12];
        Wm = (const float*)d_in[13]; bm = (const float*)d_in[14];
        Ws = (const float*)d_in[15]; bs = (const float*)d_in[16];
        done = (const int*)d_in[17];
    }

    float* out = (float*)d_out;

    bf16 *p_hb, *p_h0b, *p_W1b, *p_W2b, *p_y1, *p_y2;
    float* p_c;
    cudaGetSymbolAddress((void**)&p_hb, g_hb);
    cudaGetSymbolAddress((void**)&p_h0b, g_h0b);
    cudaGetSymbolAddress((void**)&p_W1b, g_W1b);
    cudaGetSymbolAddress((void**)&p_W2b, g_W2b);
    cudaGetSymbolAddress((void**)&p_y1, g_y1);
    cudaGetSymbolAddress((void**)&p_y2, g_y2);
    cudaGetSymbolAddress((void**)&p_c, g_c);

    // 0. prep: bf16 packed weights, x, h0
    prep_wc<<<(G4 * KC + 255) / 256, 256>>>(W_hh, W_ih, b_ih, b_hh);
    prep_w12<<<(M1 * HH + M2 * M1 + 255) / 256, 256>>>(W1, W2);
    {
        size_t n = (size_t)TB * OBS + (size_t)BB * HH;
        prep_xh<<<(unsigned)((n + 255) / 256), 256>>>(x, h0);
    }

    // 1. sequential LSTM (tensor-core steps)
    for (int t = 0; t < TT; t++) {
        const bf16* hp = t ? (p_hb + (size_t)(t - 1) * BB * HH) : p_h0b;
        const float* cp = t ? p_c : c0;
        lstm_step_mma<<<dim3(BB / 64, G4 / 128), 256>>>(hp, cp, done + (size_t)t * BB, t);
    }

    // 2. LN stats (LN applied inside mlp1 A-load)
    ln_stats<<<TB / 8, 256>>>();

    // 3. MLP (bf16 mma, ELU fused)
    mlp_mma<HH, M1, true><<<dim3(TB / 64, M1 / 128), 256>>>(p_hb, p_W1b, b1, p_y1, ln_g, ln_b);
    mlp_mma<M1, M2, false><<<dim3(TB / 64, M2 / 128), 256>>>(p_y1, p_W2b, b2, p_y2, nullptr, nullptr);

    // 4. heads
    heads_kernel<<<TB / 16, 384>>>(Wm, bm, Ws, bs, out);
}

// round 6
// speedup vs baseline: 3.4403x; 1.0007x over previous
#include <cuda_runtime.h>
#include <cuda_bf16.h>
#include <math.h>
#include <stdint.h>

#define TT 64
#define BB 2048
#define OBS 48
#define HH 256
#define G4 1024
#define KC 304            // combined K = HH + OBS
#define M1 512
#define M2 256
#define TB (TT*BB)
#define LOG2PI 1.8378770664093453f

typedef __nv_bfloat16 bf16;

// ---------------- scratch (device globals: allocation-free) ----------------
__device__ __align__(16) bf16 g_Wc[G4 * KC];          // combined [Whh|Wih], [n=j*4+g][k]
__device__ float            g_bias[G4];               // b_ih + b_hh, gate-interleaved
__device__ __align__(16) bf16 g_W1b[M1 * HH];         // [n][k]
__device__ __align__(16) bf16 g_W2b[M2 * M1];         // [n][k]
__device__ __align__(16) bf16 g_xb[(size_t)TB * OBS];
__device__ __align__(16) bf16 g_h0b[BB * HH];
__device__ __align__(16) bf16 g_hb[(size_t)TB * HH];  // all h outputs, bf16
__device__ float            g_c[BB * HH];
__device__ float            g_mu[TB];
__device__ float            g_rs[TB];
__device__ __align__(16) bf16 g_y1[(size_t)TB * M1];
__device__ __align__(16) bf16 g_y2[(size_t)TB * M2];

// ---------------- mma helper ----------------
__device__ __forceinline__ void mma16816(float c[4],
    uint32_t a0, uint32_t a1, uint32_t a2, uint32_t a3,
    uint32_t b0, uint32_t b1)
{
    asm volatile(
        "mma.sync.aligned.m16n8k16.row.col.f32.bf16.bf16.f32 "
        "{%0,%1,%2,%3}, {%4,%5,%6,%7}, {%8,%9}, {%0,%1,%2,%3};"
        : "+f"(c[0]), "+f"(c[1]), "+f"(c[2]), "+f"(c[3])
        : "r"(a0), "r"(a1), "r"(a2), "r"(a3), "r"(b0), "r"(b1));
}

__device__ __forceinline__ float sigmoidf_(float x) {
    return 1.0f / (1.0f + __expf(-x));
}

#define AS_STRIDE 24
#define BS_STRIDE 24
#define CS_STRIDE 132

// ---------------- prep kernels ----------------
__global__ void prep_wc(const float* __restrict__ W_hh, const float* __restrict__ W_ih,
                        const float* __restrict__ b_ih, const float* __restrict__ b_hh)
{
    int idx = blockIdx.x * blockDim.x + threadIdx.x;
    if (idx >= G4 * KC) return;
    int n = idx / KC, k = idx % KC;
    int g = n & 3, j = n >> 2;
    float v = (k < HH) ? W_hh[(size_t)(g * HH + j) * HH + k]
                       : W_ih[(size_t)(g * HH + j) * OBS + (k - HH)];
    g_Wc[idx] = __float2bfloat16(v);
    if (k == 0) g_bias[n] = b_ih[g * HH + j] + b_hh[g * HH + j];
}

__global__ void prep_w12(const float* __restrict__ W1, const float* __restrict__ W2)
{
    int idx = blockIdx.x * blockDim.x + threadIdx.x;
    if (idx >= M1 * HH + M2 * M1) return;
    if (idx < M1 * HH) {
        int n = idx / HH, k = idx % HH;     // W1: [HH][M1] -> [n][k]
        g_W1b[idx] = __float2bfloat16(W1[(size_t)k * M1 + n]);
    } else {
        int i = idx - M1 * HH;
        int n = i / M1, k = i % M1;         // W2: [M1][M2] -> [n][k]
        g_W2b[i] = __float2bfloat16(W2[(size_t)k * M2 + n]);
    }
}

__global__ void prep_xh(const float* __restrict__ x, const float* __restrict__ h0)
{
    size_t idx = (size_t)blockIdx.x * blockDim.x + threadIdx.x;
    size_t nx = (size_t)TB * OBS;
    if (idx < nx) g_xb[idx] = __float2bfloat16(x[idx]);
    else if (idx < nx + (size_t)BB * HH) {
        size_t i = idx - nx;
        g_h0b[i] = __float2bfloat16(h0[i]);
    }
}

// ---------------- LSTM step (bf16 mma) ----------------
// C[64 x 128] tile of gates = A[64 x 304] x B[304 x 128]
// A = [h*keep | x_t] bf16, B = gate-interleaved combined weights.
__global__ __launch_bounds__(256) void lstm_step_mma(
    const bf16* __restrict__ hprev, const float* __restrict__ cprev,
    const int* __restrict__ done_t, int t)
{
    __shared__ bf16  as[64 * AS_STRIDE];
    __shared__ bf16  bs[128 * BS_STRIDE];
    __shared__ float csm[64 * CS_STRIDE];
    __shared__ float bias_s[128];

    const int tid = threadIdx.x;
    const int b0 = blockIdx.x * 64;
    const int n0 = blockIdx.y * 128;
    const bf16* xb_t = g_xb + (size_t)t * BB * OBS;

    if (tid < 128) bias_s[tid] = g_bias[n0 + tid];

    // A loader: each thread fills 4 bf16 of one row per chunk
    const int arow = tid >> 2;
    const int aseg = tid & 3;
    const int keepA = 1 - done_t[b0 + arow];
    const bf16* hrow = hprev + (size_t)(b0 + arow) * HH + aseg * 4;
    const bf16* xrow = xb_t + (size_t)(b0 + arow) * OBS + aseg * 4;
    // B loader: each thread fills 8 bf16 of one n-row per chunk
    const int bn = tid >> 1;
    const int bh = tid & 1;
    const bf16* wrow = g_Wc + (size_t)(n0 + bn) * KC + bh * 8;

    const int lane = tid & 31;
    const int warp = tid >> 5;
    const int wm = warp & 1, wn = warp >> 1;    // 2 x 4 warp grid
    const int g8 = lane >> 2, t4 = lane & 3;

    float acc[2][4][4];
#pragma unroll
    for (int i = 0; i < 2; i++)
#pragma unroll
        for (int j = 0; j < 4; j++)
#pragma unroll
            for (int k = 0; k < 4; k++) acc[i][j][k] = 0.0f;

    // prefetch chunk 0
    uint2 aReg;
    uint4 bReg;
    {
        aReg = *(const uint2*)hrow;           // kt = 0 (< HH)
        if (!keepA) { aReg.x = 0u; aReg.y = 0u; }
        bReg = *(const uint4*)wrow;
    }

#pragma unroll 1
    for (int ch = 0; ch < KC / 16; ch++) {
        __syncthreads();
        *(uint2*)&as[arow * AS_STRIDE + aseg * 4] = aReg;
        *(uint4*)&bs[bn * BS_STRIDE + bh * 8]    = bReg;
        __syncthreads();

        if (ch < KC / 16 - 1) {
            int kt = (ch + 1) * 16;
            if (kt < HH) {
                aReg = *(const uint2*)(hrow + kt);
                if (!keepA) { aReg.x = 0u; aReg.y = 0u; }
            } else {
                aReg = *(const uint2*)(xrow + (kt - HH));
            }
            bReg = *(const uint4*)(wrow + kt);
        }

        uint32_t af[2][4];
#pragma unroll
        for (int am = 0; am < 2; am++) {
            const bf16* ap = &as[(wm * 32 + am * 16 + g8) * AS_STRIDE + t4 * 2];
            af[am][0] = *(const uint32_t*)ap;
            af[am][1] = *(const uint32_t*)(ap + 8 * AS_STRIDE);
            af[am][2] = *(const uint32_t*)(ap + 8);
            af[am][3] = *(const uint32_t*)(ap + 8 * AS_STRIDE + 8);
        }
#pragma unroll
        for (int an = 0; an < 4; an++) {
            const bf16* bp = &bs[(wn * 32 + an * 8 + g8) * BS_STRIDE + t4 * 2];
            uint32_t b0v = *(const uint32_t*)bp;
            uint32_t b1v = *(const uint32_t*)(bp + 8);
#pragma unroll
            for (int am = 0; am < 2; am++)
                mma16816(acc[am][an], af[am][0], af[am][1], af[am][2], af[am][3], b0v, b1v);
        }
    }

    // C -> smem
#pragma unroll
    for (int am = 0; am < 2; am++)
#pragma unroll
        for (int an = 0; an < 4; an++) {
            int r = wm * 32 + am * 16 + g8;
            int c = wn * 32 + an * 8 + t4 * 2;
            *(float2*)&csm[r * CS_STRIDE + c]       = make_float2(acc[am][an][0], acc[am][an][1]);
            *(float2*)&csm[(r + 8) * CS_STRIDE + c] = make_float2(acc[am][an][2], acc[am][an][3]);
        }
    __syncthreads();

    // gate fusion epilogue: 64 rows x 32 j per block
    bf16* hout = g_hb + (size_t)t * BB * HH;
    const int j0 = n0 >> 2;
#pragma unroll
    for (int i = 0; i < 8; i++) {
        int p = i * 256 + tid;
        int bl = p >> 5, jl = p & 31;
        float4 gq = *(const float4*)&csm[bl * CS_STRIDE + jl * 4];
        float gi = gq.x + bias_s[jl * 4 + 0];
        float gf = gq.y + bias_s[jl * 4 + 1];
        float gg = gq.z + bias_s[jl * 4 + 2];
        float go = gq.w + bias_s[jl * 4 + 3];
        int b = b0 + bl;
        int j = j0 + jl;
        float kb = 1.0f - (float)done_t[b];
        float cold = cprev[b * HH + j] * kb;
        float cn = sigmoidf_(gf) * cold + sigmoidf_(gi) * tanhf(gg);
        float hn = sigmoidf_(go) * tanhf(cn);
        g_c[b * HH + j] = cn;
        hout[(size_t)b * HH + j] = __float2bfloat16(hn);
    }
}

// ---------------- LayerNorm stats (per row of g_hb) ----------------
__global__ __launch_bounds__(256) void ln_stats()
{
    int row = blockIdx.x * 8 + (threadIdx.x >> 5);
    int lane = threadIdx.x & 31;
    uint4 u = *(const uint4*)(g_hb + (size_t)row * HH + lane * 8);
    const __nv_bfloat162* p = (const __nv_bfloat162*)&u;
    float s = 0.0f, s2 = 0.0f;
#pragma unroll
    for (int i = 0; i < 4; i++) {
        float2 f = __bfloat1622float2(p[i]);
        s += f.x + f.y;
        s2 += f.x * f.x + f.y * f.y;
    }
#pragma unroll
    for (int o = 16; o; o >>= 1) {
        s  += __shfl_xor_sync(0xffffffffu, s, o);
        s2 += __shfl_xor_sync(0xffffffffu, s2, o);
    }
    if (lane == 0) {
        float mu = s * (1.0f / HH);
        float var = s2 * (1.0f / HH) - mu * mu;
        g_mu[row] = mu;
        g_rs[row] = rsqrtf(var + 1e-5f);
    }
}

// ---------------- MLP GEMM (bf16 mma): Out = ELU(A @ B^T + bias) ----------------
// A rows optionally LayerNorm-transformed on load. B stored [n][k].
template <int KD, int ND, bool LNA>
__global__ __launch_bounds__(256) void mlp_mma(
    const bf16* __restrict__ A, const bf16* __restrict__ Bw,
    const float* __restrict__ bias, bf16* __restrict__ Out,
    const float* __restrict__ gamma, const float* __restrict__ beta)
{
    __shared__ bf16 as[64 * AS_STRIDE];
    __shared__ bf16 bs[128 * BS_STRIDE];

    const int tid = threadIdx.x;
    const size_t m0 = (size_t)blockIdx.x * 64;
    const int n0 = blockIdx.y * 128;

    const int arow = tid >> 2;
    const int aseg = tid & 3;
    const bf16* arp = A + (m0 + arow) * KD + aseg * 4;
    float mur = 0.0f, rsr = 0.0f;
    if (LNA) { mur = g_mu[m0 + arow]; rsr = g_rs[m0 + arow]; }

    const int bn = tid >> 1;
    const int bh = tid & 1;
    const bf16* wrow = Bw + (size_t)(n0 + bn) * KD + bh * 8;

    const int lane = tid & 31;
    const int warp = tid >> 5;
    const int wm = warp & 1, wn = warp >> 1;
    const int g8 = lane >> 2, t4 = lane & 3;

    float acc[2][4][4];
#pragma unroll
    for (int i = 0; i < 2; i++)
#pragma unroll
        for (int j = 0; j < 4; j++)
#pragma unroll
            for (int k = 0; k < 4; k++) acc[i][j][k] = 0.0f;

    uint2 aReg;
    uint4 bReg;

    auto loadA = [&](int kt) {
        uint2 v = *(const uint2*)(arp + kt);
        if (LNA) {
            __nv_bfloat162* vp = (__nv_bfloat162*)&v;
            int kb = kt + aseg * 4;
            float2 f0 = __bfloat1622float2(vp[0]);
            float2 f1 = __bfloat1622float2(vp[1]);
            f0.x = (f0.x - mur) * rsr * __ldg(&gamma[kb + 0]) + __ldg(&beta[kb + 0]);
            f0.y = (f0.y - mur) * rsr * __ldg(&gamma[kb + 1]) + __ldg(&beta[kb + 1]);
            f1.x = (f1.x - mur) * rsr * __ldg(&gamma[kb + 2]) + __ldg(&beta[kb + 2]);
            f1.y = (f1.y - mur) * rsr * __ldg(&gamma[kb + 3]) + __ldg(&beta[kb + 3]);
            vp[0] = __floats2bfloat162_rn(f0.x, f0.y);
            vp[1] = __floats2bfloat162_rn(f1.x, f1.y);
        }
        aReg = v;
    };

    loadA(0);
    bReg = *(const uint4*)wrow;

#pragma unroll 1
    for (int ch = 0; ch < KD / 16; ch++) {
        __syncthreads();
        *(uint2*)&as[arow * AS_STRIDE + aseg * 4] = aReg;
        *(uint4*)&bs[bn * BS_STRIDE + bh * 8]    = bReg;
        __syncthreads();

        if (ch < KD / 16 - 1) {
            loadA((ch + 1) * 16);
            bReg = *(const uint4*)(wrow + (ch + 1) * 16);
        }

        uint32_t af[2][4];
#pragma unroll
        for (int am = 0; am < 2; am++) {
            const bf16* ap = &as[(wm * 32 + am * 16 + g8) * AS_STRIDE + t4 * 2];
            af[am][0] = *(const uint32_t*)ap;
            af[am][1] = *(const uint32_t*)(ap + 8 * AS_STRIDE);
            af[am][2] = *(const uint32_t*)(ap + 8);
            af[am][3] = *(const uint32_t*)(ap + 8 * AS_STRIDE + 8);
        }
#pragma unroll
        for (int an = 0; an < 4; an++) {
            const bf16* bp = &bs[(wn * 32 + an * 8 + g8) * BS_STRIDE + t4 * 2];
            uint32_t b0v = *(const uint32_t*)bp;
            uint32_t b1v = *(const uint32_t*)(bp + 8);
#pragma unroll
            for (int am = 0; am < 2; am++)
                mma16816(acc[am][an], af[am][0], af[am][1], af[am][2], af[am][3], b0v, b1v);
        }
    }

    // epilogue: bias + ELU + pack bf16, direct to global
#pragma unroll
    for (int am = 0; am < 2; am++)
#pragma unroll
        for (int an = 0; an < 4; an++) {
            size_t r = m0 + wm * 32 + am * 16 + g8;
            int c = n0 + wn * 32 + an * 8 + t4 * 2;
            float bc0 = __ldg(&bias[c]), bc1 = __ldg(&bias[c + 1]);
            float v0 = acc[am][an][0] + bc0;
            float v1 = acc[am][an][1] + bc1;
            v0 = (v0 > 0.0f) ? v0 : expm1f(v0);
            v1 = (v1 > 0.0f) ? v1 : expm1f(v1);
            *(__nv_bfloat162*)(Out + r * ND + c) = __floats2bfloat162_rn(v0, v1);
            float v2 = acc[am][an][2] + bc0;
            float v3 = acc[am][an][3] + bc1;
            v2 = (v2 > 0.0f) ? v2 : expm1f(v2);
            v3 = (v3 > 0.0f) ? v3 : expm1f(v3);
            *(__nv_bfloat162*)(Out + (r + 8) * ND + c) = __floats2bfloat162_rn(v2, v3);
        }
}

// ---------------- heads: mean, logp, entropy ----------------
__global__ __launch_bounds__(384) void heads_kernel(
    const float* __restrict__ Wm, const float* __restrict__ bm,
    const float* __restrict__ Ws, const float* __restrict__ bs,
    float* __restrict__ out)
{
    __shared__ float wc[M2][24];
    __shared__ float ys[16][M2 + 1];
    __shared__ float ls[16][12];
    int tid = threadIdx.x;
    for (int i = tid; i < M2 * 12; i += 384) {
        int k = i / 12, o = i % 12;
        wc[k][o] = Wm[i];
        wc[k][o + 12] = Ws[i];
    }
    int n0 = blockIdx.x * 16;
    for (int i = tid; i < 16 * 32; i += 384) {
        int r = i >> 5, seg = i & 31;
        uint4 u = *(const uint4*)(g_y2 + (size_t)(n0 + r) * M2 + seg * 8);
        const __nv_bfloat162* p = (const __nv_bfloat162*)&u;
#pragma unroll
        for (int q = 0; q < 4; q++) {
            float2 f = __bfloat1622float2(p[q]);
            ys[r][seg * 8 + 2 * q]     = f.x;
            ys[r][seg * 8 + 2 * q + 1] = f.y;
        }
    }
    __syncthreads();
    int r = tid / 24, o = tid % 24;
    float acc = 0.0f;
#pragma unroll 8
    for (int k = 0; k < M2; k++) acc += ys[r][k] * wc[k][o];
    if (o < 12) {
        out[(size_t)(n0 + r) * 14 + o] = acc + bm[o];
    } else {
        float l = acc + bs[o - 12];
        l = fminf(fmaxf(l, -5.0f), 2.0f);
        ls[r][o - 12] = l;
    }
    __syncthreads();
    if (o == 0) {
        float S = 0.0f;
#pragma unroll
        for (int i = 0; i < 12; i++) S += ls[r][i];
        out[(size_t)(n0 + r) * 14 + 12] = -S - 6.0f * LOG2PI;
        out[(size_t)(n0 + r) * 14 + 13] = S + 6.0f + 6.0f * LOG2PI;
    }
}

// ---------------- launch ----------------
extern "C" void kernel_launch(void* const* d_in, const int* in_sizes, int n_in,
                              void* d_out, int out_size)
{
    const float *x, *h0, *c0, *W_ih, *W_hh, *b_ih, *b_hh, *ln_g, *ln_b;
    const float *W1, *b1, *W2, *b2, *Wm, *bm, *Ws, *bs;
    const int* done;

    if (in_sizes[1] == TT * BB) {
        // setup_inputs dict order
        x = (const float*)d_in[0];  done = (const int*)d_in[1];
        h0 = (const float*)d_in[2]; c0 = (const float*)d_in[3];
        W_ih = (const float*)d_in[4]; W_hh = (const float*)d_in[5];
        b_ih = (const float*)d_in[6]; b_hh = (const float*)d_in[7];
        ln_g = (const float*)d_in[8]; ln_b = (const float*)d_in[9];
        W1 = (const float*)d_in[10]; b1 = (const float*)d_in[11];
        W2 = (const float*)d_in[12]; b2 = (const float*)d_in[13];
        Wm = (const float*)d_in[14]; bm = (const float*)d_in[15];
        Ws = (const float*)d_in[16]; bs = (const float*)d_in[17];
    } else {
        // reference() signature order
        x = (const float*)d_in[0];
        h0 = (const float*)d_in[1]; c0 = (const float*)d_in[2];
        W_ih = (const float*)d_in[3]; W_hh = (const float*)d_in[4];
        b_ih = (const float*)d_in[5]; b_hh = (const float*)d_in[6];
        ln_g = (const float*)d_in[7]; ln_b = (const float*)d_in[8];
        W1 = (const float*)d_in[9];  b1 = (const float*)d_in[10];
        W2 = (const float*)d_in[11]; b2 = (const float*)d_in[12];
        Wm = (const float*)d_in[13]; bm = (const float*)d_in[14];
        Ws = (const float*)d_in[15]; bs = (const float*)d_in[16];
        done = (const int*)d_in[17];
    }

    float* out = (float*)d_out;

    bf16 *p_hb, *p_h0b, *p_W1b, *p_W2b, *p_y1, *p_y2;
    float* p_c;
    cudaGetSymbolAddress((void**)&p_hb, g_hb);
    cudaGetSymbolAddress((void**)&p_h0b, g_h0b);
    cudaGetSymbolAddress((void**)&p_W1b, g_W1b);
    cudaGetSymbolAddress((void**)&p_W2b, g_W2b);
    cudaGetSymbolAddress((void**)&p_y1, g_y1);
    cudaGetSymbolAddress((void**)&p_y2, g_y2);
    cudaGetSymbolAddress((void**)&p_c, g_c);

    // 0. prep: bf16 packed weights, x, h0
    prep_wc<<<(G4 * KC + 255) / 256, 256>>>(W_hh, W_ih, b_ih, b_hh);
    prep_w12<<<(M1 * HH + M2 * M1 + 255) / 256, 256>>>(W1, W2);
    {
        size_t n = (size_t)TB * OBS + (size_t)BB * HH;
        prep_xh<<<(unsigned)((n + 255) / 256), 256>>>(x, h0);
    }

    // 1. sequential LSTM (tensor-core steps)
    for (int t = 0; t < TT; t++) {
        const bf16* hp = t ? (p_hb + (size_t)(t - 1) * BB * HH) : p_h0b;
        const float* cp = t ? p_c : c0;
        lstm_step_mma<<<dim3(BB / 64, G4 / 128), 256>>>(hp, cp, done + (size_t)t * BB, t);
    }

    // 2. LN stats (LN applied inside mlp1 A-load)
    ln_stats<<<TB / 8, 256>>>();

    // 3. MLP (bf16 mma, ELU fused)
    mlp_mma<HH, M1, true><<<dim3(TB / 64, M1 / 128), 256>>>(p_hb, p_W1b, b1, p_y1, ln_g, ln_b);
    mlp_mma<M1, M2, false><<<dim3(TB / 64, M2 / 128), 256>>>(p_y1, p_W2b, b2, p_y2, nullptr, nullptr);

    // 4. heads
    heads_kernel<<<TB / 16, 384>>>(Wm, bm, Ws, bs, out);
}

// round 9
// speedup vs baseline: 5.1795x; 1.5055x over previous
#include <cuda_runtime.h>
#include <cuda_bf16.h>
#include <math.h>
#include <stdint.h>

#define TT 64
#define BB 2048
#define OBS 48
#define HH 256
#define G4 1024
#define KC 304            // combined K = HH + OBS
#define M1 512
#define M2 256
#define TB (TT*BB)
#define LOG2PI 1.8378770664093453f

typedef __nv_bfloat16 bf16;

// ---------------- scratch (device globals: allocation-free) ----------------
__device__ __align__(16) bf16 g_Wc[G4 * KC];          // combined [Whh|Wih], [n=j*4+g][k]
__device__ float            g_bias[G4];               // b_ih + b_hh, gate-interleaved
__device__ __align__(16) bf16 g_W1b[M1 * HH];         // [n][k]
__device__ __align__(16) bf16 g_W2b[M2 * M1];         // [n][k]
__device__ __align__(16) bf16 g_xb[(size_t)TB * OBS];
__device__ __align__(16) bf16 g_hb[(size_t)TB * HH];  // all h outputs, bf16 (unmasked)
__device__ float            g_mu[TB];
__device__ float            g_rs[TB];
__device__ __align__(16) bf16 g_y1[(size_t)TB * M1];
__device__ __align__(16) bf16 g_y2[(size_t)TB * M2];

// ---------------- helpers ----------------
__device__ __forceinline__ uint32_t bf2_as_u32(__nv_bfloat162 v) {
    return *reinterpret_cast<uint32_t*>(&v);
}

__device__ __forceinline__ void mma16816(float c[4],
    uint32_t a0, uint32_t a1, uint32_t a2, uint32_t a3,
    uint32_t b0, uint32_t b1)
{
    asm volatile(
        "mma.sync.aligned.m16n8k16.row.col.f32.bf16.bf16.f32 "
        "{%0,%1,%2,%3}, {%4,%5,%6,%7}, {%8,%9}, {%0,%1,%2,%3};"
        : "+f"(c[0]), "+f"(c[1]), "+f"(c[2]), "+f"(c[3])
        : "r"(a0), "r"(a1), "r"(a2), "r"(a3), "r"(b0), "r"(b1));
}

__device__ __forceinline__ void ldsm4(uint32_t& r0, uint32_t& r1,
                                      uint32_t& r2, uint32_t& r3, uint32_t addr)
{
    asm volatile("ldmatrix.sync.aligned.m8n8.x4.shared.b16 {%0,%1,%2,%3}, [%4];"
                 : "=r"(r0), "=r"(r1), "=r"(r2), "=r"(r3) : "r"(addr));
}

__device__ __forceinline__ uint32_t smem_u32(const void* p) {
    uint32_t a;
    asm("{ .reg .u64 t; cvta.to.shared.u64 t, %1; cvt.u32.u64 %0, t; }"
        : "=r"(a) : "l"(p));
    return a;
}

__device__ __forceinline__ float tanha(float x) {
    float r; asm("tanh.approx.f32 %0, %1;" : "=f"(r) : "f"(x)); return r;
}
__device__ __forceinline__ float sigm(float x) {
    return fmaf(0.5f, tanha(0.5f * x), 0.5f);
}

#define AS_STRIDE 24
#define BS_STRIDE 24

// ---------------- prep kernels ----------------
__global__ void prep_wc(const float* __restrict__ W_hh, const float* __restrict__ W_ih,
                        const float* __restrict__ b_ih, const float* __restrict__ b_hh)
{
    int idx = blockIdx.x * blockDim.x + threadIdx.x;
    if (idx >= G4 * KC) return;
    int n = idx / KC, k = idx % KC;
    int g = n & 3, j = n >> 2;
    float v = (k < HH) ? W_hh[(size_t)(g * HH + j) * HH + k]
                       : W_ih[(size_t)(g * HH + j) * OBS + (k - HH)];
    g_Wc[idx] = __float2bfloat16(v);
    if (k == 0) g_bias[n] = b_ih[g * HH + j] + b_hh[g * HH + j];
}

__global__ void prep_w12(const float* __restrict__ W1, const float* __restrict__ W2)
{
    int idx = blockIdx.x * blockDim.x + threadIdx.x;
    if (idx >= M1 * HH + M2 * M1) return;
    if (idx < M1 * HH) {
        int n = idx / HH, k = idx % HH;
        g_W1b[idx] = __float2bfloat16(W1[(size_t)k * M1 + n]);
    } else {
        int i = idx - M1 * HH;
        int n = i / M1, k = i % M1;
        g_W2b[i] = __float2bfloat16(W2[(size_t)k * M2 + n]);
    }
}

__global__ void prep_x(const float* __restrict__ x)
{
    size_t idx = (size_t)blockIdx.x * blockDim.x + threadIdx.x;
    if (idx < (size_t)TB * OBS) g_xb[idx] = __float2bfloat16(x[idx]);
}

// ---------------- persistent cluster LSTM ----------------
// 32 clusters x 4 CTAs. Cluster owns 64 batch rows; CTA rank owns gate cols
// n in [rank*256, rank*256+256) i.e. j in [rank*64, rank*64+64).
// Per step: C[64x256] = A[64x304] x B  (ldmatrix + mma.sync, bf16),
// register epilogue (shfl gate regroup, tanh.approx, c in regs),
// h exchange via st.shared::cluster + barrier.cluster.

// smem layout (bytes):
#define SM_BIAS  0                      // 256 f32 = 1024
#define SM_A     1024                   // 64 rows x 656B (stride 328 bf16) = 41984
#define SM_STAGE 43008                  // 64 rows x 144B (stride 72 bf16)  = 9216
#define SM_B     52224                  // 256 rows x 656B                  = 167936
#define SM_TOTAL 220160
#define ASTR_B 656
#define STG_B  144

__global__ void __launch_bounds__(256, 1) __cluster_dims__(4, 1, 1)
lstm_persist(const float* __restrict__ h0, const float* __restrict__ c0,
             const int* __restrict__ done)
{
    extern __shared__ char smx[];
    const uint32_t smb = smem_u32(smx);

    const int tid = threadIdx.x;
    const int lane = tid & 31, warp = tid >> 5;
    const int wm = warp & 1, wn = warp >> 1;      // 2 x 4 warp grid (m x n)
    const int g8 = lane >> 2, t4 = lane & 3;

    uint32_t rank;
    asm("mov.u32 %0, %%cluster_ctarank;" : "=r"(rank));
    const int b0 = (blockIdx.x >> 2) * 64;
    const int jbase = rank * 64;

    float* bias_s = (float*)(smx + SM_BIAS);

    // ---- init: bias, B (static weights), A(h0|x0), c regs ----
    bias_s[tid] = g_bias[rank * 256 + tid];

    for (int u = tid; u < 256 * 38; u += 256) {
        int n = u / 38, off = u % 38;
        uint4 v = *(const uint4*)((const char*)g_Wc + (size_t)(rank * 256 + n) * 608 + off * 16);
        *(uint4*)(smx + SM_B + n * ASTR_B + off * 16) = v;
    }
    for (int u = tid; u < 4096; u += 256) {      // h0: 64 rows x 256 f32 -> bf16
        int row = u >> 6, c4 = u & 63;
        float4 v = *(const float4*)(h0 + (size_t)(b0 + row) * HH + c4 * 4);
        uint2 p;
        p.x = bf2_as_u32(__floats2bfloat162_rn(v.x, v.y));
        p.y = bf2_as_u32(__floats2bfloat162_rn(v.z, v.w));
        *(uint2*)(smx + SM_A + row * ASTR_B + c4 * 8) = p;
    }
    {   // x(t=0) into A cols 256..303
        const uint4* xs = (const uint4*)(g_xb + ((size_t)0 * BB + b0) * OBS);
        for (int u = tid; u < 384; u += 256) {
            uint4 v = xs[u];
            int e = u * 8, row = e / 48, col = e % 48;
            *(uint4*)(smx + SM_A + row * ASTR_B + 512 + col * 2) = v;
        }
    }
    // c in registers: 16 cells per thread, fixed (b,j) mapping across all steps
    float creg[16];
#pragma unroll
    for (int am = 0; am < 2; am++)
#pragma unroll
        for (int an = 0; an < 8; an++) {
            int r = wm * 32 + am * 16 + g8 + (t4 & 1) * 8;
            int jl = wn * 16 + an * 2 + (t4 >> 1);
            creg[am * 8 + an] = c0[(size_t)(b0 + r) * HH + jbase + jl];
        }
    __syncthreads();

    // ldmatrix per-lane base addresses
    const int mi = lane >> 3;
    const int rowoff = ((mi & 1) << 3) + (lane & 7);
    const uint32_t kboff = (uint32_t)((mi >> 1) << 4);
    uint32_t aBase[2], bBase[4];
#pragma unroll
    for (int am = 0; am < 2; am++)
        aBase[am] = smb + SM_A + (wm * 32 + am * 16 + rowoff) * ASTR_B + kboff;
#pragma unroll
    for (int p = 0; p < 4; p++)
        bBase[p] = smb + SM_B + (wn * 64 + p * 16 + rowoff) * ASTR_B + kboff;

    // peer A base addresses (all 4 cluster ranks, incl. self)
    uint32_t peerA[4];
#pragma unroll
    for (int r = 0; r < 4; r++) {
        uint32_t a;
        asm("mapa.shared::cluster.u32 %0, %1, %2;" : "=r"(a) : "r"(smb + SM_A), "r"(r));
        peerA[r] = a;
    }

    // ---- time loop ----
#pragma unroll 1
    for (int t = 0; t < TT; t++) {
        const int* dt = done + (size_t)t * BB + b0;
        const int base_r = wm * 32 + g8;
        int d0 = dt[base_r], d1 = dt[base_r + 8];
        int d2 = dt[base_r + 16], d3 = dt[base_r + 24];
        uint32_t m0 = d0 ? 0u : ~0u, m1 = d1 ? 0u : ~0u;
        uint32_t m2 = d2 ? 0u : ~0u, m3 = d3 ? 0u : ~0u;

        float acc[2][8][4];
#pragma unroll
        for (int i = 0; i < 2; i++)
#pragma unroll
            for (int j = 0; j < 8; j++)
#pragma unroll
                for (int k = 0; k < 4; k++) acc[i][j][k] = 0.0f;

#pragma unroll
        for (int ch = 0; ch < 19; ch++) {
            uint32_t a[2][4];
            ldsm4(a[0][0], a[0][1], a[0][2], a[0][3], aBase[0] + ch * 32);
            ldsm4(a[1][0], a[1][1], a[1][2], a[1][3], aBase[1] + ch * 32);
            if (ch < 16) {   // mask h rows (done -> zero); x chunks 16-18 unmasked
                a[0][0] &= m0; a[0][2] &= m0; a[0][1] &= m1; a[0][3] &= m1;
                a[1][0] &= m2; a[1][2] &= m2; a[1][1] &= m3; a[1][3] &= m3;
            }
#pragma unroll
            for (int p = 0; p < 4; p++) {
                uint32_t br0, br1, br2, br3;
                ldsm4(br0, br1, br2, br3, bBase[p] + ch * 32);
#pragma unroll
                for (int am = 0; am < 2; am++) {
                    mma16816(acc[am][2 * p],     a[am][0], a[am][1], a[am][2], a[am][3], br0, br2);
                    mma16816(acc[am][2 * p + 1], a[am][0], a[am][1], a[am][2], a[am][3], br1, br3);
                }
            }
        }

        __syncthreads();                                    // CTA done reading A
        asm volatile("barrier.cluster.arrive.aligned;" ::: "memory");   // B1 arrive

        // prefetch next x tile into regs
        uint4 xr0, xr1;
        const bool hx = (t < TT - 1);
        if (hx) {
            const uint4* xs = (const uint4*)(g_xb + ((size_t)(t + 1) * BB + b0) * OBS);
            xr0 = xs[tid];
            if (tid < 128) xr1 = xs[tid + 256];
        }

        // register epilogue: regroup gates via shfl, update c, compute h -> staging
        const bool odd = (t4 & 1);
#pragma unroll
        for (int am = 0; am < 2; am++) {
            const int dlo = (am == 0) ? d0 : d2;
            const int dhi = (am == 0) ? d1 : d3;
            const int dflag = odd ? dhi : dlo;
#pragma unroll
            for (int an = 0; an < 8; an++) {
                float* a = acc[am][an];
                float e0 = __shfl_xor_sync(0xffffffffu, a[0], 1);
                float e1 = __shfl_xor_sync(0xffffffffu, a[1], 1);
                float e2 = __shfl_xor_sync(0xffffffffu, a[2], 1);
                float e3 = __shfl_xor_sync(0xffffffffu, a[3], 1);
                float q0, q1, q2, q3;
                if (!odd) { q0 = a[0]; q1 = a[1]; q2 = e0; q3 = e1; }
                else      { q0 = e2;   q1 = e3;   q2 = a[2]; q3 = a[3]; }
                int jl = wn * 16 + an * 2 + (t4 >> 1);
                float4 bb = *(const float4*)&bias_s[jl * 4];
                float gi = q0 + bb.x, gf = q1 + bb.y, gg = q2 + bb.z, go = q3 + bb.w;
                int cell = am * 8 + an;
                float cold = dflag ? 0.0f : creg[cell];
                float cn = sigm(gf) * cold + sigm(gi) * tanha(gg);
                creg[cell] = cn;
                float hn = sigm(go) * tanha(cn);
                int r = wm * 32 + am * 16 + g8 + (odd ? 8 : 0);
                *(bf16*)(smx + SM_STAGE + r * STG_B + jl * 2) = __float2bfloat16(hn);
            }
        }

        // write next x into own A (only this CTA reads its x cols)
        if (hx) {
            int e = tid * 8;
            *(uint4*)(smx + SM_A + (e / 48) * ASTR_B + 512 + (e % 48) * 2) = xr0;
            if (tid < 128) {
                int e2 = (tid + 256) * 8;
                *(uint4*)(smx + SM_A + (e2 / 48) * ASTR_B + 512 + (e2 % 48) * 2) = xr1;
            }
        }

        __syncthreads();                                    // staging + x visible
        asm volatile("barrier.cluster.wait.aligned;" ::: "memory");     // B1 wait

        // push own h slice to all 4 cluster A buffers + unmasked slice to g_hb
#pragma unroll
        for (int q = 0; q < 2; q++) {
            int u = tid + q * 256;
            int row = u >> 3, off = u & 7;
            uint4 v = *(const uint4*)(smx + SM_STAGE + row * STG_B + off * 16);
#pragma unroll
            for (int r = 0; r < 4; r++) {
                uint32_t da = peerA[r] + row * ASTR_B + jbase * 2 + off * 16;
                asm volatile("st.shared::cluster.v4.b32 [%0], {%1,%2,%3,%4};"
                             :: "r"(da), "r"(v.x), "r"(v.y), "r"(v.z), "r"(v.w) : "memory");
            }
            *(uint4*)(g_hb + ((size_t)t * BB + b0 + row) * HH + jbase + off * 8) = v;
        }

        asm volatile("barrier.cluster.arrive.aligned;" ::: "memory");   // B2
        asm volatile("barrier.cluster.wait.aligned;" ::: "memory");
    }
}

// ---------------- LayerNorm stats (per row of g_hb) ----------------
__global__ __launch_bounds__(256) void ln_stats()
{
    int row = blockIdx.x * 8 + (threadIdx.x >> 5);
    int lane = threadIdx.x & 31;
    uint4 u = *(const uint4*)(g_hb + (size_t)row * HH + lane * 8);
    const __nv_bfloat162* p = (const __nv_bfloat162*)&u;
    float s = 0.0f, s2 = 0.0f;
#pragma unroll
    for (int i = 0; i < 4; i++) {
        float2 f = __bfloat1622float2(p[i]);
        s += f.x + f.y;
        s2 += f.x * f.x + f.y * f.y;
    }
#pragma unroll
    for (int o = 16; o; o >>= 1) {
        s  += __shfl_xor_sync(0xffffffffu, s, o);
        s2 += __shfl_xor_sync(0xffffffffu, s2, o);
    }
    if (lane == 0) {
        float mu = s * (1.0f / HH);
        float var = s2 * (1.0f / HH) - mu * mu;
        g_mu[row] = mu;
        g_rs[row] = rsqrtf(var + 1e-5f);
    }
}

// ---------------- MLP GEMM (bf16 mma): Out = ELU(A @ B^T + bias) ----------------
template <int KD, int ND, bool LNA>
__global__ __launch_bounds__(256) void mlp_mma(
    const bf16* __restrict__ A, const bf16* __restrict__ Bw,
    const float* __restrict__ bias, bf16* __restrict__ Out,
    const float* __restrict__ gamma, const float* __restrict__ beta)
{
    __shared__ bf16 as[64 * AS_STRIDE];
    __shared__ bf16 bs[128 * BS_STRIDE];

    const int tid = threadIdx.x;
    const size_t m0 = (size_t)blockIdx.x * 64;
    const int n0 = blockIdx.y * 128;

    const int arow = tid >> 2;
    const int aseg = tid & 3;
    const bf16* arp = A + (m0 + arow) * KD + aseg * 4;
    float mur = 0.0f, rsr = 0.0f;
    if (LNA) { mur = g_mu[m0 + arow]; rsr = g_rs[m0 + arow]; }

    const int bn = tid >> 1;
    const int bh = tid & 1;
    const bf16* wrow = Bw + (size_t)(n0 + bn) * KD + bh * 8;

    const int lane = tid & 31;
    const int warp = tid >> 5;
    const int wm = warp & 1, wn = warp >> 1;
    const int g8 = lane >> 2, t4 = lane & 3;

    float acc[2][4][4];
#pragma unroll
    for (int i = 0; i < 2; i++)
#pragma unroll
        for (int j = 0; j < 4; j++)
#pragma unroll
            for (int k = 0; k < 4; k++) acc[i][j][k] = 0.0f;

    uint2 aReg;
    uint4 bReg;

    auto loadA = [&](int kt) {
        uint2 v = *(const uint2*)(arp + kt);
        if (LNA) {
            __nv_bfloat162* vp = (__nv_bfloat162*)&v;
            int kb = kt + aseg * 4;
            float2 f0 = __bfloat1622float2(vp[0]);
            float2 f1 = __bfloat1622float2(vp[1]);
            f0.x = (f0.x - mur) * rsr * __ldg(&gamma[kb + 0]) + __ldg(&beta[kb + 0]);
            f0.y = (f0.y - mur) * rsr * __ldg(&gamma[kb + 1]) + __ldg(&beta[kb + 1]);
            f1.x = (f1.x - mur) * rsr * __ldg(&gamma[kb + 2]) + __ldg(&beta[kb + 2]);
            f1.y = (f1.y - mur) * rsr * __ldg(&gamma[kb + 3]) + __ldg(&beta[kb + 3]);
            vp[0] = __floats2bfloat162_rn(f0.x, f0.y);
            vp[1] = __floats2bfloat162_rn(f1.x, f1.y);
        }
        aReg = v;
    };

    loadA(0);
    bReg = *(const uint4*)wrow;

#pragma unroll 1
    for (int ch = 0; ch < KD / 16; ch++) {
        __syncthreads();
        *(uint2*)&as[arow * AS_STRIDE + aseg * 4] = aReg;
        *(uint4*)&bs[bn * BS_STRIDE + bh * 8]    = bReg;
        __syncthreads();

        if (ch < KD / 16 - 1) {
            loadA((ch + 1) * 16);
            bReg = *(const uint4*)(wrow + (ch + 1) * 16);
        }

        uint32_t af[2][4];
#pragma unroll
        for (int am = 0; am < 2; am++) {
            const bf16* ap = &as[(wm * 32 + am * 16 + g8) * AS_STRIDE + t4 * 2];
            af[am][0] = *(const uint32_t*)ap;
            af[am][1] = *(const uint32_t*)(ap + 8 * AS_STRIDE);
            af[am][2] = *(const uint32_t*)(ap + 8);
            af[am][3] = *(const uint32_t*)(ap + 8 * AS_STRIDE + 8);
        }
#pragma unroll
        for (int an = 0; an < 4; an++) {
            const bf16* bp = &bs[(wn * 32 + an * 8 + g8) * BS_STRIDE + t4 * 2];
            uint32_t b0v = *(const uint32_t*)bp;
            uint32_t b1v = *(const uint32_t*)(bp + 8);
#pragma unroll
            for (int am = 0; am < 2; am++)
                mma16816(acc[am][an], af[am][0], af[am][1], af[am][2], af[am][3], b0v, b1v);
        }
    }

#pragma unroll
    for (int am = 0; am < 2; am++)
#pragma unroll
        for (int an = 0; an < 4; an++) {
            size_t r = m0 + wm * 32 + am * 16 + g8;
            int c = n0 + wn * 32 + an * 8 + t4 * 2;
            float bc0 = __ldg(&bias[c]), bc1 = __ldg(&bias[c + 1]);
            float v0 = acc[am][an][0] + bc0;
            float v1 = acc[am][an][1] + bc1;
            v0 = (v0 > 0.0f) ? v0 : expm1f(v0);
            v1 = (v1 > 0.0f) ? v1 : expm1f(v1);
            *(__nv_bfloat162*)(Out + r * ND + c) = __floats2bfloat162_rn(v0, v1);
            float v2 = acc[am][an][2] + bc0;
            float v3 = acc[am][an][3] + bc1;
            v2 = (v2 > 0.0f) ? v2 : expm1f(v2);
            v3 = (v3 > 0.0f) ? v3 : expm1f(v3);
            *(__nv_bfloat162*)(Out + (r + 8) * ND + c) = __floats2bfloat162_rn(v2, v3);
        }
}

// ---------------- heads: mean, logp, entropy ----------------
__global__ __launch_bounds__(384) void heads_kernel(
    const float* __restrict__ Wm, const float* __restrict__ bm,
    const float* __restrict__ Ws, const float* __restrict__ bs,
    float* __restrict__ out)
{
    __shared__ float wc[M2][24];
    __shared__ float ys[16][M2 + 1];
    __shared__ float ls[16][12];
    int tid = threadIdx.x;
    for (int i = tid; i < M2 * 12; i += 384) {
        int k = i / 12, o = i % 12;
        wc[k][o] = Wm[i];
        wc[k][o + 12] = Ws[i];
    }
    int n0 = blockIdx.x * 16;
    for (int i = tid; i < 16 * 32; i += 384) {
        int r = i >> 5, seg = i & 31;
        uint4 u = *(const uint4*)(g_y2 + (size_t)(n0 + r) * M2 + seg * 8);
        const __nv_bfloat162* p = (const __nv_bfloat162*)&u;
#pragma unroll
        for (int q = 0; q < 4; q++) {
            float2 f = __bfloat1622float2(p[q]);
            ys[r][seg * 8 + 2 * q]     = f.x;
            ys[r][seg * 8 + 2 * q + 1] = f.y;
        }
    }
    __syncthreads();
    int r = tid / 24, o = tid % 24;
    float acc = 0.0f;
#pragma unroll 8
    for (int k = 0; k < M2; k++) acc += ys[r][k] * wc[k][o];
    if (o < 12) {
        out[(size_t)(n0 + r) * 14 + o] = acc + bm[o];
    } else {
        float l = acc + bs[o - 12];
        l = fminf(fmaxf(l, -5.0f), 2.0f);
        ls[r][o - 12] = l;
    }
    __syncthreads();
    if (o == 0) {
        float S = 0.0f;
#pragma unroll
        for (int i = 0; i < 12; i++) S += ls[r][i];
        out[(size_t)(n0 + r) * 14 + 12] = -S - 6.0f * LOG2PI;
        out[(size_t)(n0 + r) * 14 + 13] = S + 6.0f + 6.0f * LOG2PI;
    }
}

// ---------------- launch ----------------
extern "C" void kernel_launch(void* const* d_in, const int* in_sizes, int n_in,
                              void* d_out, int out_size)
{
    const float *x, *h0, *c0, *W_ih, *W_hh, *b_ih, *b_hh, *ln_g, *ln_b;
    const float *W1, *b1, *W2, *b2, *Wm, *bm, *Ws, *bs;
    const int* done;

    if (in_sizes[1] == TT * BB) {
        // setup_inputs dict order
        x = (const float*)d_in[0];  done = (const int*)d_in[1];
        h0 = (const float*)d_in[2]; c0 = (const float*)d_in[3];
        W_ih = (const float*)d_in[4]; W_hh = (const float*)d_in[5];
        b_ih = (const float*)d_in[6]; b_hh = (const float*)d_in[7];
        ln_g = (const float*)d_in[8]; ln_b = (const float*)d_in[9];
        W1 = (const float*)d_in[10]; b1 = (const float*)d_in[11];
        W2 = (const float*)d_in[12]; b2 = (const float*)d_in[13];
        Wm = (const float*)d_in[14]; bm = (const float*)d_in[15];
        Ws = (const float*)d_in[16]; bs = (const float*)d_in[17];
    } else {
        // reference() signature order
        x = (const float*)d_in[0];
        h0 = (const float*)d_in[1]; c0 = (const float*)d_in[2];
        W_ih = (const float*)d_in[3]; W_hh = (const float*)d_in[4];
        b_ih = (const float*)d_in[5]; b_hh = (const float*)d_in[6];
        ln_g = (const float*)d_in[7]; ln_b = (const float*)d_in[8];
        W1 = (const float*)d_in[9];  b1 = (const float*)d_in[10];
        W2 = (const float*)d_in[11]; b2 = (const float*)d_in[12];
        Wm = (const float*)d_in[13]; bm = (const float*)d_in[14];
        Ws = (const float*)d_in[15]; bs = (const float*)d_in[16];
        done = (const int*)d_in[17];
    }

    float* out = (float*)d_out;

    bf16 *p_hb, *p_W1b, *p_W2b, *p_y1, *p_y2;
    cudaGetSymbolAddress((void**)&p_hb, g_hb);
    cudaGetSymbolAddress((void**)&p_W1b, g_W1b);
    cudaGetSymbolAddress((void**)&p_W2b, g_W2b);
    cudaGetSymbolAddress((void**)&p_y1, g_y1);
    cudaGetSymbolAddress((void**)&p_y2, g_y2);

    cudaFuncSetAttribute(lstm_persist, cudaFuncAttributeMaxDynamicSharedMemorySize, SM_TOTAL);

    // 0. prep: bf16 packed weights + x
    prep_wc<<<(G4 * KC + 255) / 256, 256>>>(W_hh, W_ih, b_ih, b_hh);
    prep_w12<<<(M1 * HH + M2 * M1 + 255) / 256, 256>>>(W1, W2);
    prep_x<<<(unsigned)(((size_t)TB * OBS + 255) / 256), 256>>>(x);

    // 1. persistent cluster LSTM (single launch, all 64 steps)
    lstm_persist<<<128, 256, SM_TOTAL>>>(h0, c0, done);

    // 2. LN stats (LN applied inside mlp1 A-load)
    ln_stats<<<TB / 8, 256>>>();

    // 3. MLP (bf16 mma, ELU fused)
    mlp_mma<HH, M1, true><<<dim3(TB / 64, M1 / 128), 256>>>(p_hb, p_W1b, b1, p_y1, ln_g, ln_b);
    mlp_mma<M1, M2, false><<<dim3(TB / 64, M2 / 128), 256>>>(p_y1, p_W2b, b2, p_y2, nullptr, nullptr);

    // 4. heads
    heads_kernel<<<TB / 16, 384>>>(Wm, bm, Ws, bs, out);
}

// round 10
// speedup vs baseline: 6.3471x; 1.2254x over previous
#include <cuda_runtime.h>
#include <cuda_bf16.h>
#include <math.h>
#include <stdint.h>

#define TT 64
#define BB 2048
#define OBS 48
#define HH 256
#define G4 1024
#define KC 304            // combined K = HH + OBS
#define M1 512
#define M2 256
#define TB (TT*BB)
#define LOG2PI 1.8378770664093453f

typedef __nv_bfloat16 bf16;

// ---------------- scratch (device globals: allocation-free) ----------------
__device__ __align__(16) bf16 g_Wc[G4 * KC];          // combined [Whh|Wih], [n=j*4+g][k]
__device__ float            g_bias[G4];               // b_ih + b_hh, gate-interleaved
__device__ __align__(16) bf16 g_W1b[M1 * HH];         // [n][k]
__device__ __align__(16) bf16 g_W2b[M2 * M1];         // [n][k]
__device__ __align__(16) bf16 g_xb[(size_t)TB * OBS];
__device__ __align__(16) bf16 g_hb[(size_t)TB * HH];  // all h outputs, bf16 (unmasked)
__device__ float            g_mu[TB];
__device__ float            g_rs[TB];
__device__ __align__(16) bf16 g_y1[(size_t)TB * M1];

// ---------------- helpers ----------------
__device__ __forceinline__ uint32_t bf2_as_u32(__nv_bfloat162 v) {
    return *reinterpret_cast<uint32_t*>(&v);
}

__device__ __forceinline__ void mma16816(float c[4],
    uint32_t a0, uint32_t a1, uint32_t a2, uint32_t a3,
    uint32_t b0, uint32_t b1)
{
    asm volatile(
        "mma.sync.aligned.m16n8k16.row.col.f32.bf16.bf16.f32 "
        "{%0,%1,%2,%3}, {%4,%5,%6,%7}, {%8,%9}, {%0,%1,%2,%3};"
        : "+f"(c[0]), "+f"(c[1]), "+f"(c[2]), "+f"(c[3])
        : "r"(a0), "r"(a1), "r"(a2), "r"(a3), "r"(b0), "r"(b1));
}

__device__ __forceinline__ void ldsm4(uint32_t& r0, uint32_t& r1,
                                      uint32_t& r2, uint32_t& r3, uint32_t addr)
{
    asm volatile("ldmatrix.sync.aligned.m8n8.x4.shared.b16 {%0,%1,%2,%3}, [%4];"
                 : "=r"(r0), "=r"(r1), "=r"(r2), "=r"(r3) : "r"(addr));
}

__device__ __forceinline__ uint32_t smem_u32(const void* p) {
    uint32_t a;
    asm("{ .reg .u64 t; cvta.to.shared.u64 t, %1; cvt.u32.u64 %0, t; }"
        : "=r"(a) : "l"(p));
    return a;
}

__device__ __forceinline__ float tanha(float x) {
    float r; asm("tanh.approx.f32 %0, %1;" : "=f"(r) : "f"(x)); return r;
}
__device__ __forceinline__ float sigm(float x) {
    return fmaf(0.5f, tanha(0.5f * x), 0.5f);
}

// ---------------- prep kernels ----------------
__global__ void prep_wc(const float* __restrict__ W_hh, const float* __restrict__ W_ih,
                        const float* __restrict__ b_ih, const float* __restrict__ b_hh)
{
    int idx = blockIdx.x * blockDim.x + threadIdx.x;
    if (idx >= G4 * KC) return;
    int n = idx / KC, k = idx % KC;
    int g = n & 3, j = n >> 2;
    float v = (k < HH) ? W_hh[(size_t)(g * HH + j) * HH + k]
                       : W_ih[(size_t)(g * HH + j) * OBS + (k - HH)];
    g_Wc[idx] = __float2bfloat16(v);
    if (k == 0) g_bias[n] = b_ih[g * HH + j] + b_hh[g * HH + j];
}

__global__ void prep_w12(const float* __restrict__ W1, const float* __restrict__ W2)
{
    int idx = blockIdx.x * blockDim.x + threadIdx.x;
    if (idx >= M1 * HH + M2 * M1) return;
    if (idx < M1 * HH) {
        int n = idx / HH, k = idx % HH;
        g_W1b[idx] = __float2bfloat16(W1[(size_t)k * M1 + n]);
    } else {
        int i = idx - M1 * HH;
        int n = i / M1, k = i % M1;
        g_W2b[i] = __float2bfloat16(W2[(size_t)k * M2 + n]);
    }
}

__global__ void prep_x(const float* __restrict__ x)
{
    size_t idx = (size_t)blockIdx.x * blockDim.x + threadIdx.x;
    if (idx < (size_t)TB * OBS) g_xb[idx] = __float2bfloat16(x[idx]);
}

// ---------------- persistent cluster LSTM ----------------
#define SM_BIAS  0
#define SM_A     1024
#define SM_STAGE 43008
#define SM_B     52224
#define SM_TOTAL 220160
#define ASTR_B 656
#define STG_B  144

__global__ void __launch_bounds__(256, 1) __cluster_dims__(4, 1, 1)
lstm_persist(const float* __restrict__ h0, const float* __restrict__ c0,
             const int* __restrict__ done)
{
    extern __shared__ char smx[];
    const uint32_t smb = smem_u32(smx);

    const int tid = threadIdx.x;
    const int lane = tid & 31, warp = tid >> 5;
    const int wm = warp & 1, wn = warp >> 1;      // 2 x 4 warp grid (m x n)
    const int g8 = lane >> 2, t4 = lane & 3;

    uint32_t rank;
    asm("mov.u32 %0, %%cluster_ctarank;" : "=r"(rank));
    const int b0 = (blockIdx.x >> 2) * 64;
    const int jbase = rank * 64;

    float* bias_s = (float*)(smx + SM_BIAS);

    // ---- init: bias, B (static weights), A(h0|x0), c regs ----
    bias_s[tid] = g_bias[rank * 256 + tid];

    for (int u = tid; u < 256 * 38; u += 256) {
        int n = u / 38, off = u % 38;
        uint4 v = *(const uint4*)((const char*)g_Wc + (size_t)(rank * 256 + n) * 608 + off * 16);
        *(uint4*)(smx + SM_B + n * ASTR_B + off * 16) = v;
    }
    for (int u = tid; u < 4096; u += 256) {      // h0: 64 rows x 256 f32 -> bf16
        int row = u >> 6, c4 = u & 63;
        float4 v = *(const float4*)(h0 + (size_t)(b0 + row) * HH + c4 * 4);
        uint2 p;
        p.x = bf2_as_u32(__floats2bfloat162_rn(v.x, v.y));
        p.y = bf2_as_u32(__floats2bfloat162_rn(v.z, v.w));
        *(uint2*)(smx + SM_A + row * ASTR_B + c4 * 8) = p;
    }
    {   // x(t=0) into A cols 256..303
        const uint4* xs = (const uint4*)(g_xb + ((size_t)0 * BB + b0) * OBS);
        for (int u = tid; u < 384; u += 256) {
            uint4 v = xs[u];
            int e = u * 8, row = e / 48, col = e % 48;
            *(uint4*)(smx + SM_A + row * ASTR_B + 512 + col * 2) = v;
        }
    }
    // c in registers: 16 cells per thread
    float creg[16];
#pragma unroll
    for (int am = 0; am < 2; am++)
#pragma unroll
        for (int an = 0; an < 8; an++) {
            int r = wm * 32 + am * 16 + g8 + (t4 & 1) * 8;
            int jl = wn * 16 + an * 2 + (t4 >> 1);
            creg[am * 8 + an] = c0[(size_t)(b0 + r) * HH + jbase + jl];
        }
    __syncthreads();

    // ldmatrix per-lane base addresses
    const int mi = lane >> 3;
    const int rowoff = ((mi & 1) << 3) + (lane & 7);
    const uint32_t kboff = (uint32_t)((mi >> 1) << 4);
    uint32_t aBase[2], bBase[4];
#pragma unroll
    for (int am = 0; am < 2; am++)
        aBase[am] = smb + SM_A + (wm * 32 + am * 16 + rowoff) * ASTR_B + kboff;
#pragma unroll
    for (int p = 0; p < 4; p++)
        bBase[p] = smb + SM_B + (wn * 64 + p * 16 + rowoff) * ASTR_B + kboff;

    // peer A base addresses
    uint32_t peerA[4];
#pragma unroll
    for (int r = 0; r < 4; r++) {
        uint32_t a;
        asm("mapa.shared::cluster.u32 %0, %1, %2;" : "=r"(a) : "r"(smb + SM_A), "r"(r));
        peerA[r] = a;
    }

    // done flags for t=0 (prefetched each step thereafter)
    const int base_r = wm * 32 + g8;
    int d0, d1, d2, d3;
    {
        const int* dt = done + b0;
        d0 = dt[base_r]; d1 = dt[base_r + 8];
        d2 = dt[base_r + 16]; d3 = dt[base_r + 24];
    }

    // ---- time loop ----
#pragma unroll 1
    for (int t = 0; t < TT; t++) {
        uint32_t m0 = d0 ? 0u : ~0u, m1 = d1 ? 0u : ~0u;
        uint32_t m2 = d2 ? 0u : ~0u, m3 = d3 ? 0u : ~0u;

        float acc[2][8][4];
#pragma unroll
        for (int i = 0; i < 2; i++)
#pragma unroll
            for (int j = 0; j < 8; j++)
#pragma unroll
                for (int k = 0; k < 4; k++) acc[i][j][k] = 0.0f;

        if (t)  // B2 from previous iteration (delayed wait)
            asm volatile("barrier.cluster.wait.aligned;" ::: "memory");

#pragma unroll
        for (int ch = 0; ch < 19; ch++) {
            uint32_t a[2][4];
            ldsm4(a[0][0], a[0][1], a[0][2], a[0][3], aBase[0] + ch * 32);
            ldsm4(a[1][0], a[1][1], a[1][2], a[1][3], aBase[1] + ch * 32);
            if (ch < 16) {   // mask h rows (done -> zero); x chunks unmasked
                a[0][0] &= m0; a[0][2] &= m0; a[0][1] &= m1; a[0][3] &= m1;
                a[1][0] &= m2; a[1][2] &= m2; a[1][1] &= m3; a[1][3] &= m3;
            }
#pragma unroll
            for (int p = 0; p < 4; p++) {
                uint32_t br0, br1, br2, br3;
                ldsm4(br0, br1, br2, br3, bBase[p] + ch * 32);
#pragma unroll
                for (int am = 0; am < 2; am++) {
                    mma16816(acc[am][2 * p],     a[am][0], a[am][1], a[am][2], a[am][3], br0, br2);
                    mma16816(acc[am][2 * p + 1], a[am][0], a[am][1], a[am][2], a[am][3], br1, br3);
                }
            }
        }

        asm volatile("barrier.cluster.arrive.aligned;" ::: "memory");   // B1 arrive

        // prefetch next x tile + next done flags
        uint4 xr0, xr1;
        int dn0 = 0, dn1 = 0, dn2 = 0, dn3 = 0;
        const bool hx = (t < TT - 1);
        if (hx) {
            const uint4* xs = (const uint4*)(g_xb + ((size_t)(t + 1) * BB + b0) * OBS);
            xr0 = xs[tid];
            if (tid < 128) xr1 = xs[tid + 256];
            const int* dt = done + (size_t)(t + 1) * BB + b0;
            dn0 = dt[base_r]; dn1 = dt[base_r + 8];
            dn2 = dt[base_r + 16]; dn3 = dt[base_r + 24];
        }

        // register epilogue: 2-shfl gate regroup, c in regs, tanh.approx
        const bool odd = (t4 & 1);
#pragma unroll
        for (int am = 0; am < 2; am++) {
            const int dlo = (am == 0) ? d0 : d2;
            const int dhi = (am == 0) ? d1 : d3;
            const int dflag = odd ? dhi : dlo;
#pragma unroll
            for (int an = 0; an < 8; an++) {
                float* a = acc[am][an];
                float s0 = odd ? a[0] : a[2];
                float s1 = odd ? a[1] : a[3];
                float e0 = __shfl_xor_sync(0xffffffffu, s0, 1);
                float e1 = __shfl_xor_sync(0xffffffffu, s1, 1);
                float q0 = odd ? e0 : a[0];
                float q1 = odd ? e1 : a[1];
                float q2 = odd ? a[2] : e0;
                float q3 = odd ? a[3] : e1;
                int jl = wn * 16 + an * 2 + (t4 >> 1);
                float4 bb = *(const float4*)&bias_s[jl * 4];
                float gi = q0 + bb.x, gf = q1 + bb.y, gg = q2 + bb.z, go = q3 + bb.w;
                int cell = am * 8 + an;
                float cold = dflag ? 0.0f : creg[cell];
                float cn = sigm(gf) * cold + sigm(gi) * tanha(gg);
                creg[cell] = cn;
                float hn = sigm(go) * tanha(cn);
                int r = wm * 32 + am * 16 + g8 + (odd ? 8 : 0);
                *(bf16*)(smx + SM_STAGE + r * STG_B + jl * 2) = __float2bfloat16(hn);
            }
        }

        // write next x into own A
        if (hx) {
            int e = tid * 8;
            *(uint4*)(smx + SM_A + (e / 48) * ASTR_B + 512 + (e % 48) * 2) = xr0;
            if (tid < 128) {
                int e2 = (tid + 256) * 8;
                *(uint4*)(smx + SM_A + (e2 / 48) * ASTR_B + 512 + (e2 % 48) * 2) = xr1;
            }
        }

        __syncthreads();                                    // staging visible
        asm volatile("barrier.cluster.wait.aligned;" ::: "memory");     // B1 wait

        // push own h slice to all 4 cluster A buffers + g_hb
#pragma unroll
        for (int q = 0; q < 2; q++) {
            int u = tid + q * 256;
            int row = u >> 3, off = u & 7;
            uint4 v = *(const uint4*)(smx + SM_STAGE + row * STG_B + off * 16);
#pragma unroll
            for (int r = 0; r < 4; r++) {
                uint32_t da = peerA[r] + row * ASTR_B + jbase * 2 + off * 16;
                asm volatile("st.shared::cluster.v4.b32 [%0], {%1,%2,%3,%4};"
                             :: "r"(da), "r"(v.x), "r"(v.y), "r"(v.z), "r"(v.w) : "memory");
            }
            *(uint4*)(g_hb + ((size_t)t * BB + b0 + row) * HH + jbase + off * 8) = v;
        }

        asm volatile("barrier.cluster.arrive.aligned;" ::: "memory");   // B2 arrive
        d0 = dn0; d1 = dn1; d2 = dn2; d3 = dn3;
    }
    asm volatile("barrier.cluster.wait.aligned;" ::: "memory");         // drain B2
}

// ---------------- LayerNorm stats (per row of g_hb) ----------------
__global__ __launch_bounds__(256) void ln_stats()
{
    int row = blockIdx.x * 8 + (threadIdx.x >> 5);
    int lane = threadIdx.x & 31;
    uint4 u = *(const uint4*)(g_hb + (size_t)row * HH + lane * 8);
    const __nv_bfloat162* p = (const __nv_bfloat162*)&u;
    float s = 0.0f, s2 = 0.0f;
#pragma unroll
    for (int i = 0; i < 4; i++) {
        float2 f = __bfloat1622float2(p[i]);
        s += f.x + f.y;
        s2 += f.x * f.x + f.y * f.y;
    }
#pragma unroll
    for (int o = 16; o; o >>= 1) {
        s  += __shfl_xor_sync(0xffffffffu, s, o);
        s2 += __shfl_xor_sync(0xffffffffu, s2, o);
    }
    if (lane == 0) {
        float mu = s * (1.0f / HH);
        float var = s2 * (1.0f / HH) - mu * mu;
        g_mu[row] = mu;
        g_rs[row] = rsqrtf(var + 1e-5f);
    }
}

// ---------------- A-hot GEMM: Out = ELU(A[64 x KD] @ Bw^T + bias) ----------------
// A tile resident in smem for the whole K loop (LN fused on load if LNA).
// B streamed in 32-K chunks. If HEADS: NT==256 covers full N; heads computed
// block-locally (mean/logp/ent) and written to outF; Out unused.
template <int KD, int NT, bool LNA, bool HEADS>
__global__ __launch_bounds__(256) void gemm_hot(
    const bf16* __restrict__ A, const bf16* __restrict__ Bw,
    const float* __restrict__ bias, bf16* __restrict__ Out,
    const float* __restrict__ gamma, const float* __restrict__ beta,
    const float* __restrict__ Wm, const float* __restrict__ bm,
    const float* __restrict__ Ws, const float* __restrict__ bsv,
    float* __restrict__ outF)
{
    constexpr int AST = KD + 8;           // A row stride (elems); (AST*2/16) odd
    constexpr int ASZ = 64 * AST * 2;     // bytes
    constexpr int P   = NT / 64;          // B ldsm groups per 16-k step
    constexpr int AN  = NT / 32;          // n atoms per warp
    constexpr int CH  = KD / 32;          // 32-K chunks
    constexpr int BLD = NT / 64;          // uint4 B transfers per thread per chunk

    extern __shared__ char sm[];
    char* smA = sm;
    char* smB = sm + ASZ;
    float* wc = (float*)(sm + ASZ + NT * 80);   // HEADS only: 24 x 260 f32

    const int tid = threadIdx.x;
    const int lane = tid & 31, warp = tid >> 5;
    const int wm = warp & 1, wn = warp >> 1;
    const int g8 = lane >> 2, t4 = lane & 3;
    const size_t m0 = (size_t)blockIdx.x * 64;
    const int n0 = blockIdx.y * NT;

    // ---- load A tile (once), LN fused ----
    for (int u = tid; u < 64 * (KD / 8); u += 256) {
        int row = u / (KD / 8), pos = u % (KD / 8);
        uint4 v = *(const uint4*)(A + (m0 + row) * KD + pos * 8);
        if (LNA) {
            float mu = g_mu[m0 + row], rs = g_rs[m0 + row];
            __nv_bfloat162* vp = (__nv_bfloat162*)&v;
            int kb = pos * 8;
#pragma unroll
            for (int q = 0; q < 4; q++) {
                float2 f = __bfloat1622float2(vp[q]);
                f.x = (f.x - mu) * rs * __ldg(&gamma[kb + 2 * q])     + __ldg(&beta[kb + 2 * q]);
                f.y = (f.y - mu) * rs * __ldg(&gamma[kb + 2 * q + 1]) + __ldg(&beta[kb + 2 * q + 1]);
                vp[q] = __floats2bfloat162_rn(f.x, f.y);
            }
        }
        *(uint4*)(smA + row * AST * 2 + pos * 16) = v;
    }

    // ---- B chunk 0 prefetch ----
    uint4 breg[BLD];
#pragma unroll
    for (int i = 0; i < BLD; i++) {
        int u = tid + i * 256;
        int row = u >> 2, q = u & 3;
        breg[i] = *(const uint4*)(Bw + (size_t)(n0 + row) * KD + q * 8);
    }

    float acc[2][AN][4];
#pragma unroll
    for (int i = 0; i < 2; i++)
#pragma unroll
        for (int j = 0; j < AN; j++)
#pragma unroll
            for (int k = 0; k < 4; k++) acc[i][j][k] = 0.0f;

    const int mi = lane >> 3;
    const int rowoff = ((mi & 1) << 3) + (lane & 7);
    const uint32_t kb16 = (uint32_t)((mi >> 1) << 4);
    const uint32_t smAu = smem_u32(smA);
    const uint32_t smBu = smem_u32(smB);
    uint32_t aB[2], bB[P];
#pragma unroll
    for (int am = 0; am < 2; am++)
        aB[am] = smAu + (wm * 32 + am * 16 + rowoff) * (AST * 2) + kb16;
#pragma unroll
    for (int p = 0; p < P; p++)
        bB[p] = smBu + (wn * (NT / 4) + p * 16 + rowoff) * 80 + kb16;

    // ---- K loop ----
#pragma unroll 1
    for (int c = 0; c < CH; c++) {
        __syncthreads();
#pragma unroll
        for (int i = 0; i < BLD; i++) {
            int u = tid + i * 256;
            int row = u >> 2, q = u & 3;
            *(uint4*)(smB + row * 80 + q * 16) = breg[i];
        }
        __syncthreads();
        if (c + 1 < CH) {
#pragma unroll
            for (int i = 0; i < BLD; i++) {
                int u = tid + i * 256;
                int row = u >> 2, q = u & 3;
                breg[i] = *(const uint4*)(Bw + (size_t)(n0 + row) * KD + (c + 1) * 32 + q * 8);
            }
        }
#pragma unroll
        for (int ks = 0; ks < 2; ks++) {
            int s = c * 2 + ks;
            uint32_t a[2][4];
            ldsm4(a[0][0], a[0][1], a[0][2], a[0][3], aB[0] + s * 32);
            ldsm4(a[1][0], a[1][1], a[1][2], a[1][3], aB[1] + s * 32);
#pragma unroll
            for (int p = 0; p < P; p++) {
                uint32_t br0, br1, br2, br3;
                ldsm4(br0, br1, br2, br3, bB[p] + ks * 32);
#pragma unroll
                for (int am = 0; am < 2; am++) {
                    mma16816(acc[am][2 * p],     a[am][0], a[am][1], a[am][2], a[am][3], br0, br2);
                    mma16816(acc[am][2 * p + 1], a[am][0], a[am][1], a[am][2], a[am][3], br1, br3);
                }
            }
        }
    }

    if (!HEADS) {
        // ---- epilogue: bias + ELU + bf16 pack -> Out ----
#pragma unroll
        for (int am = 0; am < 2; am++)
#pragma unroll
            for (int an = 0; an < AN; an++) {
                size_t r = m0 + wm * 32 + am * 16 + g8;
                int c = n0 + wn * (NT / 4) + an * 8 + t4 * 2;
                float bc0 = __ldg(&bias[c]), bc1 = __ldg(&bias[c + 1]);
                float v0 = acc[am][an][0] + bc0;
                float v1 = acc[am][an][1] + bc1;
                v0 = (v0 > 0.0f) ? v0 : expm1f(v0);
                v1 = (v1 > 0.0f) ? v1 : expm1f(v1);
                *(__nv_bfloat162*)(Out + r * (M1) + c) = __floats2bfloat162_rn(v0, v1);
                float v2 = acc[am][an][2] + bc0;
                float v3 = acc[am][an][3] + bc1;
                v2 = (v2 > 0.0f) ? v2 : expm1f(v2);
                v3 = (v3 > 0.0f) ? v3 : expm1f(v3);
                *(__nv_bfloat162*)(Out + (r + 8) * (M1) + c) = __floats2bfloat162_rn(v2, v3);
            }
    } else {
        // ---- fused heads epilogue ----
        __syncthreads();                     // all ldsm reads of A done
        float* ys = (float*)smA;             // 64 x 260 f32 (66560B == ASZ for KD=512)
#pragma unroll
        for (int am = 0; am < 2; am++)
#pragma unroll
            for (int an = 0; an < AN; an++) {
                int r = wm * 32 + am * 16 + g8;
                int c = wn * (NT / 4) + an * 8 + t4 * 2;
                float bc0 = __ldg(&bias[c]), bc1 = __ldg(&bias[c + 1]);
                float v0 = acc[am][an][0] + bc0;
                float v1 = acc[am][an][1] + bc1;
                v0 = (v0 > 0.0f) ? v0 : expm1f(v0);
                v1 = (v1 > 0.0f) ? v1 : expm1f(v1);
                *(float2*)(ys + r * 260 + c) = make_float2(v0, v1);
                float v2 = acc[am][an][2] + bc0;
                float v3 = acc[am][an][3] + bc1;
                v2 = (v2 > 0.0f) ? v2 : expm1f(v2);
                v3 = (v3 > 0.0f) ? v3 : expm1f(v3);
                *(float2*)(ys + (r + 8) * 260 + c) = make_float2(v2, v3);
            }
        // wc[o][k] transposed head weights (o<12: Wm col o; else Ws col o-12)
        for (int u = tid; u < 24 * 256; u += 256) {
            int o = u % 24, k = u / 24;
            wc[o * 260 + k] = (o < 12) ? __ldg(&Wm[k * 12 + o]) : __ldg(&Ws[k * 12 + (o - 12)]);
        }
        __syncthreads();

        int r = tid >> 2, t4h = tid & 3;
        float dot[6] = {0, 0, 0, 0, 0, 0};
#pragma unroll 4
        for (int k = 0; k < 256; k += 4) {
            float4 yv = *(const float4*)(ys + r * 260 + k);
#pragma unroll
            for (int i = 0; i < 6; i++) {
                float4 wv = *(const float4*)(wc + (t4h * 6 + i) * 260 + k);
                dot[i] += yv.x * wv.x + yv.y * wv.y + yv.z * wv.z + yv.w * wv.w;
            }
        }
        float S = 0.0f;
        if (t4h < 2) {
#pragma unroll
            for (int i = 0; i < 6; i++) {
                int o = t4h * 6 + i;
                outF[(m0 + r) * 14 + o] = dot[i] + __ldg(&bm[o]);
            }
        } else {
#pragma unroll
            for (int i = 0; i < 6; i++) {
                int o = (t4h - 2) * 6 + i;
                float l = dot[i] + __ldg(&bsv[o]);
                l = fminf(fmaxf(l, -5.0f), 2.0f);
                S += l;
            }
        }
        S += __shfl_xor_sync(0xffffffffu, S, 1);
        S += __shfl_xor_sync(0xffffffffu, S, 2);
        if (t4h == 0) {
            outF[(m0 + r) * 14 + 12] = -S - 6.0f * LOG2PI;
            outF[(m0 + r) * 14 + 13] = S + 6.0f + 6.0f * LOG2PI;
        }
    }
}

// ---------------- launch ----------------
extern "C" void kernel_launch(void* const* d_in, const int* in_sizes, int n_in,
                              void* d_out, int out_size)
{
    const float *x, *h0, *c0, *W_ih, *W_hh, *b_ih, *b_hh, *ln_g, *ln_b;
    const float *W1, *b1, *W2, *b2, *Wm, *bm, *Ws, *bs;
    const int* done;

    if (in_sizes[1] == TT * BB) {
        // setup_inputs dict order
        x = (const float*)d_in[0];  done = (const int*)d_in[1];
        h0 = (const float*)d_in[2]; c0 = (const float*)d_in[3];
        W_ih = (const float*)d_in[4]; W_hh = (const float*)d_in[5];
        b_ih = (const float*)d_in[6]; b_hh = (const float*)d_in[7];
        ln_g = (const float*)d_in[8]; ln_b = (const float*)d_in[9];
        W1 = (const float*)d_in[10]; b1 = (const float*)d_in[11];
        W2 = (const float*)d_in[12]; b2 = (const float*)d_in[13];
        Wm = (const float*)d_in[14]; bm = (const float*)d_in[15];
        Ws = (const float*)d_in[16]; bs = (const float*)d_in[17];
    } else {
        // reference() signature order
        x = (const float*)d_in[0];
        h0 = (const float*)d_in[1]; c0 = (const float*)d_in[2];
        W_ih = (const float*)d_in[3]; W_hh = (const float*)d_in[4];
        b_ih = (const float*)d_in[5]; b_hh = (const float*)d_in[6];
        ln_g = (const float*)d_in[7]; ln_b = (const float*)d_in[8];
        W1 = (const float*)d_in[9];  b1 = (const float*)d_in[10];
        W2 = (const float*)d_in[11]; b2 = (const float*)d_in[12];
        Wm = (const float*)d_in[13]; bm = (const float*)d_in[14];
        Ws = (const float*)d_in[15]; bs = (const float*)d_in[16];
        done = (const int*)d_in[17];
    }

    float* out = (float*)d_out;

    bf16 *p_hb, *p_W1b, *p_W2b, *p_y1;
    cudaGetSymbolAddress((void**)&p_hb, g_hb);
    cudaGetSymbolAddress((void**)&p_W1b, g_W1b);
    cudaGetSymbolAddress((void**)&p_W2b, g_W2b);
    cudaGetSymbolAddress((void**)&p_y1, g_y1);

    // smem sizes
    const int SM1 = 64 * (HH + 8) * 2 + 128 * 80;                     // mlp1: 44032
    const int SM2 = 64 * (M1 + 8) * 2 + 256 * 80 + 24 * 260 * 4;     // mlp2h: 111520

    cudaFuncSetAttribute(lstm_persist, cudaFuncAttributeMaxDynamicSharedMemorySize, SM_TOTAL);
    cudaFuncSetAttribute(gemm_hot<HH, 128, true, false>,
                         cudaFuncAttributeMaxDynamicSharedMemorySize, SM1);
    cudaFuncSetAttribute(gemm_hot<M1, 256, false, true>,
                         cudaFuncAttributeMaxDynamicSharedMemorySize, SM2);

    // 0. prep: bf16 packed weights + x
    prep_wc<<<(G4 * KC + 255) / 256, 256>>>(W_hh, W_ih, b_ih, b_hh);
    prep_w12<<<(M1 * HH + M2 * M1 + 255) / 256, 256>>>(W1, W2);
    prep_x<<<(unsigned)(((size_t)TB * OBS + 255) / 256), 256>>>(x);

    // 1. persistent cluster LSTM (single launch, all 64 steps)
    lstm_persist<<<128, 256, SM_TOTAL>>>(h0, c0, done);

    // 2. LN stats (applied inside mlp1 A-load)
    ln_stats<<<TB / 8, 256>>>();

    // 3. MLP1: y1 = ELU(LN(h) @ W1 + b1)
    gemm_hot<HH, 128, true, false><<<dim3(TB / 64, M1 / 128), 256, SM1>>>(
        p_hb, p_W1b, b1, p_y1, ln_g, ln_b,
        nullptr, nullptr, nullptr, nullptr, nullptr);

    // 4. MLP2 + heads fused: out = [mean, logp, ent]
    gemm_hot<M1, 256, false, true><<<dim3(TB / 64, 1), 256, SM2>>>(
        p_y1, p_W2b, b2, nullptr, nullptr, nullptr,
        Wm, bm, Ws, bs, out);
}